// round 6
// baseline (speedup 1.0000x reference)
#include <cuda_runtime.h>
#include <cuda_bf16.h>
#include <cstdint>

#define MAXB 131072

// ---------------- persistent device scratch (no runtime allocation) ----------------
__device__ __align__(16) float          g_x0[(size_t)MAXB * 2 * 64];       // [token][64]
__device__ __align__(16) unsigned char  g_wbuf[24 * 17408 + 33792];        // weight tile images

// ---------------- common helpers ----------------
static __device__ __forceinline__ uint32_t smem_u32(const void* p) {
    uint32_t a;
    asm("{ .reg .u64 t; cvta.to.shared.u64 t, %1; cvt.u32.u64 %0, t; }" : "=r"(a) : "l"(p));
    return a;
}
static __device__ __forceinline__ void ldmA(uint32_t a[4], uint32_t addr) {
    asm volatile("ldmatrix.sync.aligned.m8n8.x4.shared.b16 {%0,%1,%2,%3}, [%4];"
                 : "=r"(a[0]), "=r"(a[1]), "=r"(a[2]), "=r"(a[3]) : "r"(addr));
}
static __device__ __forceinline__ void ldmB(uint32_t b[2], uint32_t addr) {
    asm volatile("ldmatrix.sync.aligned.m8n8.x2.shared.b16 {%0,%1}, [%2];"
                 : "=r"(b[0]), "=r"(b[1]) : "r"(addr));
}
static __device__ __forceinline__ void mma16816(float d[4], const uint32_t a[4], const uint32_t b[2]) {
    asm volatile("mma.sync.aligned.m16n8k16.row.col.f32.bf16.bf16.f32 "
                 "{%0,%1,%2,%3}, {%4,%5,%6,%7}, {%8,%9}, {%0,%1,%2,%3};"
                 : "+f"(d[0]), "+f"(d[1]), "+f"(d[2]), "+f"(d[3])
                 : "r"(a[0]), "r"(a[1]), "r"(a[2]), "r"(a[3]), "r"(b[0]), "r"(b[1]));
}

// 3-term compensated D[16x64] += A[16xK] * B[64xK]^T  (strides in BYTES)
// ILP layout: 8 independent MMAs between dependent accumulator reuses.
template<int NKC>
static __device__ __forceinline__ void gemm3(float (*acc)[4], uint32_t aBase, int aStrB,
                                             uint32_t bBase, int bStrB) {
    const int lane = threadIdx.x & 31;
    const int KB = NKC * 32;
    uint32_t aAddr = aBase + (lane & 15) * aStrB + ((lane >> 4) << 4);
    uint32_t bAddr = bBase + (lane & 7) * bStrB + (((lane >> 3) & 1) << 4);
    #pragma unroll
    for (int kc = 0; kc < NKC; ++kc) {
        uint32_t ah[4], al[4];
        ldmA(ah, aAddr + kc * 32);
        ldmA(al, aAddr + kc * 32 + KB);
        uint32_t bh[8][2];
        #pragma unroll
        for (int j = 0; j < 8; ++j) ldmB(bh[j], bAddr + j * 8 * bStrB + kc * 32);
        #pragma unroll
        for (int j = 0; j < 8; ++j) mma16816(acc[j], ah, bh[j]);
        #pragma unroll
        for (int j = 0; j < 8; ++j) mma16816(acc[j], al, bh[j]);
        #pragma unroll
        for (int j = 0; j < 8; ++j) {
            uint32_t bl[2];
            ldmB(bl, bAddr + j * 8 * bStrB + kc * 32 + KB);
            mma16816(acc[j], ah, bl);
        }
    }
}

// hi/lo bf16 pair store into padded tile [r][strideElems], hi cols 0:K, lo K:2K
static __device__ __forceinline__ void st_hilo(char* sm, uint32_t off, int strideElems,
                                               int r, int c, int K, float f0, float f1) {
    __nv_bfloat16 h0 = __float2bfloat16(f0), h1 = __float2bfloat16(f1);
    __nv_bfloat162 hh; hh.x = h0; hh.y = h1;
    __nv_bfloat162 ll;
    ll.x = __float2bfloat16(f0 - __bfloat162float(h0));
    ll.y = __float2bfloat16(f1 - __bfloat162float(h1));
    __nv_bfloat16* row = (__nv_bfloat16*)(sm + off) + (size_t)r * strideElems;
    *reinterpret_cast<__nv_bfloat162*>(row + c)     = hh;
    *reinterpret_cast<__nv_bfloat162*>(row + K + c) = ll;
}

// =====================================================================================
// Pre-kernel A: convert all weights to hi/lo tile images
// =====================================================================================
__global__ void conv_w_kernel(const float* __restrict__ in_w, const float* __restrict__ out_w,
                              const float* __restrict__ ff1_w, const float* __restrict__ ff2_w,
                              const float* __restrict__ h1_w)
{
    int b = blockIdx.x;
    if (b < 24) {
        int l = b / 12, c = b % 12;
        const float* src; int rs;
        if (c < 3)       { src = in_w  + ((size_t)l * 192 + 64 * c) * 64; rs = 64; }
        else if (c == 3) { src = out_w + (size_t)l * 4096;                rs = 64; }
        else {
            int cc = (c - 4) >> 1;
            if (((c - 4) & 1) == 0) { src = ff1_w + ((size_t)l * 256 + 64 * cc) * 64; rs = 64;  }
            else                    { src = ff2_w + (size_t)l * 16384 + 64 * cc;      rs = 256; }
        }
        unsigned char* dst = g_wbuf + (size_t)b * 17408;
        for (int idx = threadIdx.x; idx < 64 * 32; idx += 256) {
            int n = idx >> 5, k2 = (idx & 31) << 1;
            float2 f = *reinterpret_cast<const float2*>(src + (size_t)n * rs + k2);
            __nv_bfloat16 h0 = __float2bfloat16(f.x), h1 = __float2bfloat16(f.y);
            __nv_bfloat162 hh; hh.x = h0; hh.y = h1;
            __nv_bfloat162 ll;
            ll.x = __float2bfloat16(f.x - __bfloat162float(h0));
            ll.y = __float2bfloat16(f.y - __bfloat162float(h1));
            *reinterpret_cast<__nv_bfloat162*>(dst + n * 272 + k2 * 2)       = hh;
            *reinterpret_cast<__nv_bfloat162*>(dst + n * 272 + 128 + k2 * 2) = ll;
        }
    } else {
        unsigned char* dst = g_wbuf + 24 * 17408;
        for (int idx = threadIdx.x; idx < 64 * 64; idx += 256) {
            int n = idx >> 6, k2 = (idx & 63) << 1;
            float2 f = *reinterpret_cast<const float2*>(h1_w + (size_t)n * 128 + k2);
            __nv_bfloat16 h0 = __float2bfloat16(f.x), h1 = __float2bfloat16(f.y);
            __nv_bfloat162 hh; hh.x = h0; hh.y = h1;
            __nv_bfloat162 ll;
            ll.x = __float2bfloat16(f.x - __bfloat162float(h0));
            ll.y = __float2bfloat16(f.y - __bfloat162float(h1));
            *reinterpret_cast<__nv_bfloat162*>(dst + n * 528 + k2 * 2)       = hh;
            *reinterpret_cast<__nv_bfloat162*>(dst + n * 528 + 256 + k2 * 2) = ll;
        }
    }
}

// =====================================================================================
// Pre-kernel B: embedding projection -> g_x0[token][64]
// =====================================================================================
#define EB_FEAT 0u
#define EB_WU   67584u
#define EB_WI   101376u
#define EB_SIDX 135168u
#define EB_SMEM 135680u

static __device__ void stage_hilo128(char* sm, uint32_t off, const float* __restrict__ w,
                                     int nRows, int tid) {
    for (int idx = tid; idx < nRows * 64; idx += 256) {
        int n = idx >> 6, k2 = (idx & 63) << 1;
        float2 f = *reinterpret_cast<const float2*>(w + (size_t)n * 128 + k2);
        __nv_bfloat16 h0 = __float2bfloat16(f.x), h1 = __float2bfloat16(f.y);
        __nv_bfloat162 hh; hh.x = h0; hh.y = h1;
        __nv_bfloat162 ll;
        ll.x = __float2bfloat16(f.x - __bfloat162float(h0));
        ll.y = __float2bfloat16(f.y - __bfloat162float(h1));
        char* row = sm + off + (size_t)n * 528;
        *reinterpret_cast<__nv_bfloat162*>(row + k2 * 2)       = hh;
        *reinterpret_cast<__nv_bfloat162*>(row + 256 + k2 * 2) = ll;
    }
}

__global__ void __launch_bounds__(256, 1)
embed_kernel(const int* __restrict__ user_idx, const int* __restrict__ item_idx,
             const float* __restrict__ user_features, const float* __restrict__ item_features,
             const float* __restrict__ user_table, const float* __restrict__ item_table,
             const float* __restrict__ upw, const float* __restrict__ upb,
             const float* __restrict__ ipw, const float* __restrict__ ipb,
             const float* __restrict__ pe)
{
    extern __shared__ char sm[];
    const int tid = threadIdx.x, lane = tid & 31, w = tid >> 5;
    const int s0 = blockIdx.x << 6;
    int* sidx = (int*)(sm + EB_SIDX);

    if (tid < 64)       sidx[tid] = user_idx[s0 + tid];
    else if (tid < 128) sidx[tid] = item_idx[s0 + tid - 64];

    stage_hilo128(sm, EB_FEAT,               user_features + (size_t)s0 * 128, 64, tid);
    stage_hilo128(sm, EB_FEAT + 64u * 528u,  item_features + (size_t)s0 * 128, 64, tid);
    stage_hilo128(sm, EB_WU, upw, 64, tid);
    stage_hilo128(sm, EB_WI, ipw, 64, tid);
    __syncthreads();

    float acc[8][4];
    #pragma unroll
    for (int j = 0; j < 8; ++j) { acc[j][0] = acc[j][1] = acc[j][2] = acc[j][3] = 0.f; }
    gemm3<8>(acc, smem_u32(sm + EB_FEAT) + (uint32_t)(16 * w) * 528u, 528,
             smem_u32(sm + (w < 4 ? EB_WU : EB_WI)), 528);

    const int side = w >> 2;
    const int qr = lane >> 2, qc = lane & 3;
    const int r0 = 16 * w + qr;
    const int sA = side ? r0 - 64 : r0;
    const int sB = sA + 8;
    const float* bb  = side ? ipb : upb;
    const float* tbl = side ? item_table : user_table;
    const float* pep = pe + side * 64;
    size_t tA = (size_t)sidx[side * 64 + sA] * 64;
    size_t tB = (size_t)sidx[side * 64 + sB] * 64;
    float* dA = g_x0 + ((size_t)(s0 + sA) * 2 + side) * 64;
    float* dB = g_x0 + ((size_t)(s0 + sB) * 2 + side) * 64;
    #pragma unroll
    for (int j = 0; j < 8; ++j) {
        int c = 8 * j + 2 * qc;
        dA[c]     = acc[j][0] + __ldg(bb + c)     + __ldg(tbl + tA + c)     + __ldg(pep + c);
        dA[c + 1] = acc[j][1] + __ldg(bb + c + 1) + __ldg(tbl + tA + c + 1) + __ldg(pep + c + 1);
        dB[c]     = acc[j][2] + __ldg(bb + c)     + __ldg(tbl + tB + c)     + __ldg(pep + c);
        dB[c + 1] = acc[j][3] + __ldg(bb + c + 1) + __ldg(tbl + tB + c + 1) + __ldg(pep + c + 1);
    }
}

// =====================================================================================
// Main kernel: 256 threads, 64 samples (128 token rows), 2 CTAs/SM (16 warps/SM)
// smem: XT [128][272B] @0 | CT [128][272B] @34816 | WB 2x17408 @69632   total 104448
// =====================================================================================
#define XT_OFF 0u
#define CT_OFF 34816u
#define WB_OFF 69632u
#define MAIN_SMEM 104448u
#define MT 256

#define CP16(dst, src) asm volatile("cp.async.cg.shared.global [%0], [%1], 16;" \
                                    :: "r"(dst), "l"(src) : "memory")
#define CP_COMMIT() asm volatile("cp.async.commit_group;" ::: "memory")
#define CP_WAIT0()  asm volatile("cp.async.wait_group 0;" ::: "memory")

static __device__ __forceinline__ void stage_cp(uint32_t dst, const unsigned char* src,
                                                int bytes, int tid) {
    for (int o = tid * 16; o < bytes; o += MT * 16)
        CP16(dst + o, src + o);
}

// LN over one register row (16 vals/lane over 4 qc lanes), write hi/lo tile
static __device__ __forceinline__ void ln_reg(float v[8][2], const float* g, const float* b,
                                              char* sm, uint32_t off, int strideE,
                                              int row, int colbase, int K, int qc)
{
    float s = 0.f;
    #pragma unroll
    for (int j = 0; j < 8; ++j) s += v[j][0] + v[j][1];
    s += __shfl_xor_sync(0xffffffffu, s, 1);
    s += __shfl_xor_sync(0xffffffffu, s, 2);
    float m = s * (1.f / 64.f);
    float var = 0.f;
    #pragma unroll
    for (int j = 0; j < 8; ++j) {
        float d0 = v[j][0] - m, d1 = v[j][1] - m;
        var += d0 * d0 + d1 * d1;
    }
    var += __shfl_xor_sync(0xffffffffu, var, 1);
    var += __shfl_xor_sync(0xffffffffu, var, 2);
    float inv = rsqrtf(var * (1.f / 64.f) + 1e-5f);
    #pragma unroll
    for (int j = 0; j < 8; ++j) {
        int cc = 8 * j + 2 * qc;
        float f0 = (v[j][0] - m) * inv * __ldg(g + cc)     + __ldg(b + cc);
        float f1 = (v[j][1] - m) * inv * __ldg(g + cc + 1) + __ldg(b + cc + 1);
        v[j][0] = f0; v[j][1] = f1;
        st_hilo(sm, off, strideE, row, colbase + cc, K, f0, f1);
    }
}

__global__ void __launch_bounds__(MT, 2)
main_kernel(const float* __restrict__ in_b, const float* __restrict__ out_b,
            const float* __restrict__ ln1_g, const float* __restrict__ ln1_b,
            const float* __restrict__ ff1_b, const float* __restrict__ ff2_b,
            const float* __restrict__ ln2_g, const float* __restrict__ ln2_b,
            const float* __restrict__ h1_b, const float* __restrict__ h2_w,
            const float* __restrict__ h2_b, float* __restrict__ out)
{
    extern __shared__ char sm[];
    const int tid = threadIdx.x, lane = tid & 31, w = tid >> 5;
    const int qr = lane >> 2, qc = lane & 3;
    const int rA = 16 * w + qr;               // token rows owned: rA, rA+8
    const int s0m = blockIdx.x << 6;          // first sample
    const uint32_t xt_u = smem_u32(sm + XT_OFF);
    const uint32_t ct_u = smem_u32(sm + CT_OFF);
    const uint32_t wb_u = smem_u32(sm + WB_OFF);
    const uint32_t wbuf[2] = { wb_u, wb_u + 17408u };

    // prefetch first weight chunk immediately
    stage_cp(wbuf[0], g_wbuf, 17408, tid);
    CP_COMMIT();

    // load x0 -> registers + XT tile
    float x_[2][8][2];
    {
        const float* x0p = g_x0 + (size_t)(blockIdx.x * 128) * 64;
        #pragma unroll
        for (int h = 0; h < 2; ++h) {
            int row = rA + 8 * h;
            const float* xp = x0p + (size_t)row * 64;
            #pragma unroll
            for (int j = 0; j < 8; ++j) {
                float2 f = __ldg(reinterpret_cast<const float2*>(xp + 8 * j + 2 * qc));
                x_[h][j][0] = f.x; x_[h][j][1] = f.y;
                st_hilo(sm, XT_OFF, 136, row, 8 * j + 2 * qc, 64, f.x, f.y);
            }
        }
        __syncwarp();
    }

    const uint32_t aXT = xt_u + (uint32_t)(16 * w) * 272u;
    const uint32_t aCT = ct_u + (uint32_t)(16 * w) * 272u;

    float q_[8][4];
    float wS[2][4], wO[2][4];
    float accF[8][4];
    int gidx = 0;

    for (int l = 0; l < 2; ++l) {
        for (int g = 0; g < 12; ++g) {
            CP_WAIT0();
            __syncthreads();
            if (gidx + 1 < 24) {
                stage_cp(wbuf[(gidx + 1) & 1], g_wbuf + (size_t)(gidx + 1) * 17408, 17408, tid);
                CP_COMMIT();
            }
            const uint32_t bb = wbuf[gidx & 1];

            if (g == 0) {
                // ---- q ----
                #pragma unroll
                for (int j = 0; j < 8; ++j) { q_[j][0] = q_[j][1] = q_[j][2] = q_[j][3] = 0.f; }
                gemm3<4>(q_, aXT, 272, bb, 272);
                const float* bq = in_b + l * 192;
                #pragma unroll
                for (int j = 0; j < 8; ++j) {
                    int c = 8 * j + 2 * qc;
                    float b0 = __ldg(bq + c), b1 = __ldg(bq + c + 1);
                    q_[j][0] += b0; q_[j][1] += b1; q_[j][2] += b0; q_[j][3] += b1;
                }
            } else if (g == 1) {
                // ---- k + scores + softmax ----
                float acc[8][4];
                #pragma unroll
                for (int j = 0; j < 8; ++j) { acc[j][0] = acc[j][1] = acc[j][2] = acc[j][3] = 0.f; }
                gemm3<4>(acc, aXT, 272, bb, 272);
                const float* bk = in_b + l * 192 + 64;
                #pragma unroll
                for (int j = 0; j < 8; ++j) {
                    int c = 8 * j + 2 * qc;
                    float b0 = __ldg(bk + c), b1 = __ldg(bk + c + 1);
                    acc[j][0] += b0; acc[j][1] += b1; acc[j][2] += b0; acc[j][3] += b1;
                }
                float sS[2][4], sO[2][4];
                #pragma unroll
                for (int h = 0; h < 4; ++h) {
                    int j0 = 2 * h, j1 = 2 * h + 1;
                    sS[0][h] = q_[j0][0] * acc[j0][0] + q_[j0][1] * acc[j0][1]
                             + q_[j1][0] * acc[j1][0] + q_[j1][1] * acc[j1][1];
                    sS[1][h] = q_[j0][2] * acc[j0][2] + q_[j0][3] * acc[j0][3]
                             + q_[j1][2] * acc[j1][2] + q_[j1][3] * acc[j1][3];
                    float k00 = __shfl_xor_sync(0xffffffffu, acc[j0][0], 4);
                    float k01 = __shfl_xor_sync(0xffffffffu, acc[j0][1], 4);
                    float k10 = __shfl_xor_sync(0xffffffffu, acc[j1][0], 4);
                    float k11 = __shfl_xor_sync(0xffffffffu, acc[j1][1], 4);
                    float k02 = __shfl_xor_sync(0xffffffffu, acc[j0][2], 4);
                    float k03 = __shfl_xor_sync(0xffffffffu, acc[j0][3], 4);
                    float k12 = __shfl_xor_sync(0xffffffffu, acc[j1][2], 4);
                    float k13 = __shfl_xor_sync(0xffffffffu, acc[j1][3], 4);
                    sO[0][h] = q_[j0][0] * k00 + q_[j0][1] * k01 + q_[j1][0] * k10 + q_[j1][1] * k11;
                    sO[1][h] = q_[j0][2] * k02 + q_[j0][3] * k03 + q_[j1][2] * k12 + q_[j1][3] * k13;
                }
                #pragma unroll
                for (int r = 0; r < 2; ++r)
                    #pragma unroll
                    for (int h = 0; h < 4; ++h) {
                        sS[r][h] += __shfl_xor_sync(0xffffffffu, sS[r][h], 1);
                        sS[r][h] += __shfl_xor_sync(0xffffffffu, sS[r][h], 2);
                        sO[r][h] += __shfl_xor_sync(0xffffffffu, sO[r][h], 1);
                        sO[r][h] += __shfl_xor_sync(0xffffffffu, sO[r][h], 2);
                        float a = sS[r][h] * 0.25f, o = sO[r][h] * 0.25f;
                        float m = fmaxf(a, o);
                        float ea = expf(a - m), eo = expf(o - m);
                        float inv = 1.f / (ea + eo);
                        wS[r][h] = ea * inv; wO[r][h] = eo * inv;
                    }
            } else if (g == 2) {
                // ---- v + ctx -> CT ----
                float acc[8][4];
                #pragma unroll
                for (int j = 0; j < 8; ++j) { acc[j][0] = acc[j][1] = acc[j][2] = acc[j][3] = 0.f; }
                gemm3<4>(acc, aXT, 272, bb, 272);
                const float* bv = in_b + l * 192 + 128;
                #pragma unroll
                for (int j = 0; j < 8; ++j) {
                    int c = 8 * j + 2 * qc;
                    float b0 = __ldg(bv + c), b1 = __ldg(bv + c + 1);
                    acc[j][0] += b0; acc[j][1] += b1; acc[j][2] += b0; acc[j][3] += b1;
                }
                #pragma unroll
                for (int j = 0; j < 8; ++j) {
                    int h = j >> 1, c = 8 * j + 2 * qc;
                    float p0 = __shfl_xor_sync(0xffffffffu, acc[j][0], 4);
                    float p1 = __shfl_xor_sync(0xffffffffu, acc[j][1], 4);
                    float p2 = __shfl_xor_sync(0xffffffffu, acc[j][2], 4);
                    float p3 = __shfl_xor_sync(0xffffffffu, acc[j][3], 4);
                    st_hilo(sm, CT_OFF, 136, rA, c, 64,
                            wS[0][h] * acc[j][0] + wO[0][h] * p0,
                            wS[0][h] * acc[j][1] + wO[0][h] * p1);
                    st_hilo(sm, CT_OFF, 136, rA + 8, c, 64,
                            wS[1][h] * acc[j][2] + wO[1][h] * p2,
                            wS[1][h] * acc[j][3] + wO[1][h] * p3);
                }
                __syncwarp();
            } else if (g == 3) {
                // ---- out-proj + residual + LN1 -> XT ----
                float acc[8][4];
                #pragma unroll
                for (int j = 0; j < 8; ++j) { acc[j][0] = acc[j][1] = acc[j][2] = acc[j][3] = 0.f; }
                gemm3<4>(acc, aCT, 272, bb, 272);
                const float* bo = out_b + l * 64;
                #pragma unroll
                for (int j = 0; j < 8; ++j) {
                    int c = 8 * j + 2 * qc;
                    float b0 = __ldg(bo + c), b1 = __ldg(bo + c + 1);
                    x_[0][j][0] += acc[j][0] + b0; x_[0][j][1] += acc[j][1] + b1;
                    x_[1][j][0] += acc[j][2] + b0; x_[1][j][1] += acc[j][3] + b1;
                }
                ln_reg(x_[0], ln1_g + l * 64, ln1_b + l * 64, sm, XT_OFF, 136, rA,     0, 64, qc);
                ln_reg(x_[1], ln1_g + l * 64, ln1_b + l * 64, sm, XT_OFF, 136, rA + 8, 0, 64, qc);
                __syncwarp();
            } else if (((g - 4) & 1) == 0) {
                // ---- ff1 chunk -> relu -> CT ----
                int c4 = (g - 4) >> 1;
                float acc[8][4];
                #pragma unroll
                for (int j = 0; j < 8; ++j) { acc[j][0] = acc[j][1] = acc[j][2] = acc[j][3] = 0.f; }
                gemm3<4>(acc, aXT, 272, bb, 272);
                const float* b1p = ff1_b + l * 256 + 64 * c4;
                #pragma unroll
                for (int j = 0; j < 8; ++j) {
                    int c = 8 * j + 2 * qc;
                    float b0 = __ldg(b1p + c), b1 = __ldg(b1p + c + 1);
                    st_hilo(sm, CT_OFF, 136, rA, c, 64,
                            fmaxf(acc[j][0] + b0, 0.f), fmaxf(acc[j][1] + b1, 0.f));
                    st_hilo(sm, CT_OFF, 136, rA + 8, c, 64,
                            fmaxf(acc[j][2] + b0, 0.f), fmaxf(acc[j][3] + b1, 0.f));
                }
                __syncwarp();
            } else {
                // ---- ff2 chunk accumulate ----
                int c4 = (g - 4) >> 1;
                if (c4 == 0) {
                    #pragma unroll
                    for (int j = 0; j < 8; ++j) { accF[j][0] = accF[j][1] = accF[j][2] = accF[j][3] = 0.f; }
                }
                gemm3<4>(accF, aCT, 272, bb, 272);
                if (c4 == 3) {
                    const float* b2 = ff2_b + l * 64;
                    #pragma unroll
                    for (int j = 0; j < 8; ++j) {
                        int c = 8 * j + 2 * qc;
                        float b0 = __ldg(b2 + c), b1 = __ldg(b2 + c + 1);
                        x_[0][j][0] += accF[j][0] + b0; x_[0][j][1] += accF[j][1] + b1;
                        x_[1][j][0] += accF[j][2] + b0; x_[1][j][1] += accF[j][3] + b1;
                    }
                    const float* g2 = ln2_g + l * 64;
                    const float* bL = ln2_b + l * 64;
                    if (l == 0) {
                        ln_reg(x_[0], g2, bL, sm, XT_OFF, 136, rA,     0, 64, qc);
                        ln_reg(x_[1], g2, bL, sm, XT_OFF, 136, rA + 8, 0, 64, qc);
                    } else {
                        // head layout: sample row = token>>1, col half = 64*(token&1)
                        ln_reg(x_[0], g2, bL, sm, XT_OFF, 264, rA >> 1,       64 * (rA & 1),       128, qc);
                        ln_reg(x_[1], g2, bL, sm, XT_OFF, 264, (rA + 8) >> 1, 64 * ((rA + 8) & 1), 128, qc);
                    }
                    __syncwarp();
                }
            }
            ++gidx;
        }
    }

    // ================= head =================
    CP_WAIT0();
    __syncthreads();                        // XT head tile complete; WB free
    stage_cp(wb_u, g_wbuf + 24 * 17408, 33792, tid);
    CP_COMMIT(); CP_WAIT0();
    __syncthreads();

    if (w < 4) {
        float acc[8][4];
        #pragma unroll
        for (int j = 0; j < 8; ++j) { acc[j][0] = acc[j][1] = acc[j][2] = acc[j][3] = 0.f; }
        gemm3<8>(acc, xt_u + (uint32_t)(16 * w) * 528u, 528, wb_u, 528);
        float pA = 0.f, pB = 0.f;
        #pragma unroll
        for (int j = 0; j < 8; ++j) {
            int c = 8 * j + 2 * qc;
            float b0 = __ldg(h1_b + c), b1 = __ldg(h1_b + c + 1);
            float w0 = __ldg(h2_w + c), w1 = __ldg(h2_w + c + 1);
            pA += fmaxf(acc[j][0] + b0, 0.f) * w0 + fmaxf(acc[j][1] + b1, 0.f) * w1;
            pB += fmaxf(acc[j][2] + b0, 0.f) * w0 + fmaxf(acc[j][3] + b1, 0.f) * w1;
        }
        pA += __shfl_xor_sync(0xffffffffu, pA, 1);
        pA += __shfl_xor_sync(0xffffffffu, pA, 2);
        pB += __shfl_xor_sync(0xffffffffu, pB, 1);
        pB += __shfl_xor_sync(0xffffffffu, pB, 2);
        if (qc == 0) {
            float hb = __ldg(h2_b);
            out[s0m + 16 * w + qr]     = pA + hb;
            out[s0m + 16 * w + qr + 8] = pB + hb;
        }
    }
}

// =====================================================================================
extern "C" void kernel_launch(void* const* d_in, const int* in_sizes, int n_in,
                              void* d_out, int out_size)
{
    const int*   user_idx      = (const int*)  d_in[0];
    const int*   item_idx      = (const int*)  d_in[1];
    const float* user_features = (const float*)d_in[2];
    const float* item_features = (const float*)d_in[3];
    const float* user_table    = (const float*)d_in[4];
    const float* item_table    = (const float*)d_in[5];
    const float* upw           = (const float*)d_in[6];
    const float* upb           = (const float*)d_in[7];
    const float* ipw           = (const float*)d_in[8];
    const float* ipb           = (const float*)d_in[9];
    const float* pe            = (const float*)d_in[10];
    const float* in_w          = (const float*)d_in[11];
    const float* in_b          = (const float*)d_in[12];
    const float* out_w         = (const float*)d_in[13];
    const float* out_b         = (const float*)d_in[14];
    const float* ln1_g         = (const float*)d_in[15];
    const float* ln1_b         = (const float*)d_in[16];
    const float* ff1_w         = (const float*)d_in[17];
    const float* ff1_b         = (const float*)d_in[18];
    const float* ff2_w         = (const float*)d_in[19];
    const float* ff2_b         = (const float*)d_in[20];
    const float* ln2_g         = (const float*)d_in[21];
    const float* ln2_b         = (const float*)d_in[22];
    const float* h1_w          = (const float*)d_in[23];
    const float* h1_b          = (const float*)d_in[24];
    const float* h2_w          = (const float*)d_in[25];
    const float* h2_b          = (const float*)d_in[26];
    float* out = (float*)d_out;

    const int B = in_sizes[0];

    static bool attr_set = false;
    if (!attr_set) {
        cudaFuncSetAttribute(embed_kernel, cudaFuncAttributeMaxDynamicSharedMemorySize, EB_SMEM);
        cudaFuncSetAttribute(main_kernel,  cudaFuncAttributeMaxDynamicSharedMemorySize, MAIN_SMEM);
        attr_set = true;
    }

    conv_w_kernel<<<25, 256>>>(in_w, out_w, ff1_w, ff2_w, h1_w);
    embed_kernel<<<B / 64, 256, EB_SMEM>>>(user_idx, item_idx, user_features, item_features,
                                           user_table, item_table, upw, upb, ipw, ipb, pe);
    main_kernel<<<B / 64, MT, MAIN_SMEM>>>(in_b, out_b, ln1_g, ln1_b, ff1_b, ff2_b,
                                           ln2_g, ln2_b, h1_b, h2_w, h2_b, out);
}

// round 7
// speedup vs baseline: 1.0446x; 1.0446x over previous
#include <cuda_runtime.h>
#include <cuda_bf16.h>
#include <cstdint>

#define MAXB 131072

// ---------------- persistent device scratch (no runtime allocation) ----------------
__device__ __align__(16) float          g_x0[(size_t)MAXB * 2 * 64];       // [token][64]
__device__ __align__(16) unsigned char  g_wbuf[24 * 17408 + 33792];        // weight tile images

// ---------------- common helpers ----------------
static __device__ __forceinline__ uint32_t smem_u32(const void* p) {
    uint32_t a;
    asm("{ .reg .u64 t; cvta.to.shared.u64 t, %1; cvt.u32.u64 %0, t; }" : "=r"(a) : "l"(p));
    return a;
}
static __device__ __forceinline__ void ldmA(uint32_t a[4], uint32_t addr) {
    asm volatile("ldmatrix.sync.aligned.m8n8.x4.shared.b16 {%0,%1,%2,%3}, [%4];"
                 : "=r"(a[0]), "=r"(a[1]), "=r"(a[2]), "=r"(a[3]) : "r"(addr));
}
static __device__ __forceinline__ void ldmB(uint32_t b[2], uint32_t addr) {
    asm volatile("ldmatrix.sync.aligned.m8n8.x2.shared.b16 {%0,%1}, [%2];"
                 : "=r"(b[0]), "=r"(b[1]) : "r"(addr));
}
static __device__ __forceinline__ void mma16816(float d[4], const uint32_t a[4], const uint32_t b[2]) {
    asm volatile("mma.sync.aligned.m16n8k16.row.col.f32.bf16.bf16.f32 "
                 "{%0,%1,%2,%3}, {%4,%5,%6,%7}, {%8,%9}, {%0,%1,%2,%3};"
                 : "+f"(d[0]), "+f"(d[1]), "+f"(d[2]), "+f"(d[3])
                 : "r"(a[0]), "r"(a[1]), "r"(a[2]), "r"(a[3]), "r"(b[0]), "r"(b[1]));
}

// tile-A 3-term gemm (embed + head only), strides in BYTES
template<int NKC>
static __device__ __forceinline__ void gemm3(float (*acc)[4], uint32_t aBase, int aStrB,
                                             uint32_t bBase, int bStrB) {
    const int lane = threadIdx.x & 31;
    const int KB = NKC * 32;
    uint32_t aAddr = aBase + (lane & 15) * aStrB + ((lane >> 4) << 4);
    uint32_t bAddr = bBase + (lane & 7) * bStrB + (((lane >> 3) & 1) << 4);
    #pragma unroll
    for (int kc = 0; kc < NKC; ++kc) {
        uint32_t ah[4], al[4];
        ldmA(ah, aAddr + kc * 32);
        ldmA(al, aAddr + kc * 32 + KB);
        uint32_t bh[8][2];
        #pragma unroll
        for (int j = 0; j < 8; ++j) ldmB(bh[j], bAddr + j * 8 * bStrB + kc * 32);
        #pragma unroll
        for (int j = 0; j < 8; ++j) mma16816(acc[j], ah, bh[j]);
        #pragma unroll
        for (int j = 0; j < 8; ++j) mma16816(acc[j], al, bh[j]);
        #pragma unroll
        for (int j = 0; j < 8; ++j) {
            uint32_t bl[2];
            ldmB(bl, bAddr + j * 8 * bStrB + kc * 32 + KB);
            mma16816(acc[j], ah, bl);
        }
    }
}

// register-A 3-term gemm: A fragments precomputed (K=64, 4 k-chunks), B tile stride 272B
static __device__ __forceinline__ void gemm3r(float (*acc)[4],
                                              const uint32_t fh[4][4], const uint32_t fl[4][4],
                                              uint32_t bBase) {
    const int lane = threadIdx.x & 31;
    uint32_t bAddr = bBase + (lane & 7) * 272 + (((lane >> 3) & 1) << 4);
    #pragma unroll
    for (int kc = 0; kc < 4; ++kc) {
        uint32_t bh[8][2];
        #pragma unroll
        for (int j = 0; j < 8; ++j) ldmB(bh[j], bAddr + j * 8 * 272 + kc * 32);
        #pragma unroll
        for (int j = 0; j < 8; ++j) mma16816(acc[j], fh[kc], bh[j]);
        #pragma unroll
        for (int j = 0; j < 8; ++j) mma16816(acc[j], fl[kc], bh[j]);
        #pragma unroll
        for (int j = 0; j < 8; ++j) {
            uint32_t bl[2];
            ldmB(bl, bAddr + j * 8 * 272 + kc * 32 + 128);
            mma16816(acc[j], fh[kc], bl);
        }
    }
}

// convert fp32 pair -> packed bf16 hi + packed bf16 lo
static __device__ __forceinline__ void cvt_pair(float v0, float v1, uint32_t& h, uint32_t& l) {
    __nv_bfloat162 hb = __floats2bfloat162_rn(v0, v1);
    h = *reinterpret_cast<uint32_t*>(&hb);
    float r0 = v0 - __bfloat162float(hb.x);
    float r1 = v1 - __bfloat162float(hb.y);
    __nv_bfloat162 lb = __floats2bfloat162_rn(r0, r1);
    l = *reinterpret_cast<uint32_t*>(&lb);
}

// build m16n8k16 A fragments (hi+lo) from register values v[rowhalf][j][2]
static __device__ __forceinline__ void build_fr(const float v[2][8][2],
                                                uint32_t fh[4][4], uint32_t fl[4][4]) {
    #pragma unroll
    for (int kc = 0; kc < 4; ++kc)
        #pragma unroll
        for (int m = 0; m < 4; ++m) {
            int h = m & 1, j = 2 * kc + (m >> 1);
            cvt_pair(v[h][j][0], v[h][j][1], fh[kc][m], fl[kc][m]);
        }
}

// hi/lo bf16 pair store into padded tile [r][strideElems], hi cols 0:K, lo K:2K
static __device__ __forceinline__ void st_hilo(char* sm, uint32_t off, int strideElems,
                                               int r, int c, int K, float f0, float f1) {
    __nv_bfloat16 h0 = __float2bfloat16(f0), h1 = __float2bfloat16(f1);
    __nv_bfloat162 hh; hh.x = h0; hh.y = h1;
    __nv_bfloat162 ll;
    ll.x = __float2bfloat16(f0 - __bfloat162float(h0));
    ll.y = __float2bfloat16(f1 - __bfloat162float(h1));
    __nv_bfloat16* row = (__nv_bfloat16*)(sm + off) + (size_t)r * strideElems;
    *reinterpret_cast<__nv_bfloat162*>(row + c)     = hh;
    *reinterpret_cast<__nv_bfloat162*>(row + K + c) = ll;
}

// =====================================================================================
// Pre-kernel (fused): blocks 0..24 convert weights; blocks 25.. do embedding projection
// =====================================================================================
#define EB_FEAT 0u
#define EB_WU   67584u
#define EB_WI   101376u
#define EB_SIDX 135168u
#define EB_SMEM 135680u

static __device__ void stage_hilo128(char* sm, uint32_t off, const float* __restrict__ w,
                                     int nRows, int tid) {
    for (int idx = tid; idx < nRows * 64; idx += 256) {
        int n = idx >> 6, k2 = (idx & 63) << 1;
        float2 f = *reinterpret_cast<const float2*>(w + (size_t)n * 128 + k2);
        uint32_t hh, ll;
        cvt_pair(f.x, f.y, hh, ll);
        char* row = sm + off + (size_t)n * 528;
        *reinterpret_cast<uint32_t*>(row + k2 * 2)       = hh;
        *reinterpret_cast<uint32_t*>(row + 256 + k2 * 2) = ll;
    }
}

__global__ void __launch_bounds__(256, 1)
pre_kernel(const int* __restrict__ user_idx, const int* __restrict__ item_idx,
           const float* __restrict__ user_features, const float* __restrict__ item_features,
           const float* __restrict__ user_table, const float* __restrict__ item_table,
           const float* __restrict__ upw, const float* __restrict__ upb,
           const float* __restrict__ ipw, const float* __restrict__ ipb,
           const float* __restrict__ pe,
           const float* __restrict__ in_w, const float* __restrict__ out_w,
           const float* __restrict__ ff1_w, const float* __restrict__ ff2_w,
           const float* __restrict__ h1_w)
{
    if (blockIdx.x < 25) {
        int b = blockIdx.x;
        if (b < 24) {
            int l = b / 12, c = b % 12;
            const float* src; int rs;
            if (c < 3)       { src = in_w  + ((size_t)l * 192 + 64 * c) * 64; rs = 64; }
            else if (c == 3) { src = out_w + (size_t)l * 4096;                rs = 64; }
            else {
                int cc = (c - 4) >> 1;
                if (((c - 4) & 1) == 0) { src = ff1_w + ((size_t)l * 256 + 64 * cc) * 64; rs = 64;  }
                else                    { src = ff2_w + (size_t)l * 16384 + 64 * cc;      rs = 256; }
            }
            unsigned char* dst = g_wbuf + (size_t)b * 17408;
            for (int idx = threadIdx.x; idx < 64 * 32; idx += 256) {
                int n = idx >> 5, k2 = (idx & 31) << 1;
                float2 f = *reinterpret_cast<const float2*>(src + (size_t)n * rs + k2);
                uint32_t hh, ll;
                cvt_pair(f.x, f.y, hh, ll);
                *reinterpret_cast<uint32_t*>(dst + n * 272 + k2 * 2)       = hh;
                *reinterpret_cast<uint32_t*>(dst + n * 272 + 128 + k2 * 2) = ll;
            }
        } else {
            unsigned char* dst = g_wbuf + 24 * 17408;
            for (int idx = threadIdx.x; idx < 64 * 64; idx += 256) {
                int n = idx >> 6, k2 = (idx & 63) << 1;
                float2 f = *reinterpret_cast<const float2*>(h1_w + (size_t)n * 128 + k2);
                uint32_t hh, ll;
                cvt_pair(f.x, f.y, hh, ll);
                *reinterpret_cast<uint32_t*>(dst + n * 528 + k2 * 2)       = hh;
                *reinterpret_cast<uint32_t*>(dst + n * 528 + 256 + k2 * 2) = ll;
            }
        }
        return;
    }

    extern __shared__ char sm[];
    const int tid = threadIdx.x, lane = tid & 31, w = tid >> 5;
    const int s0 = (blockIdx.x - 25) << 6;
    int* sidx = (int*)(sm + EB_SIDX);

    if (tid < 64)       sidx[tid] = user_idx[s0 + tid];
    else if (tid < 128) sidx[tid] = item_idx[s0 + tid - 64];

    stage_hilo128(sm, EB_FEAT,              user_features + (size_t)s0 * 128, 64, tid);
    stage_hilo128(sm, EB_FEAT + 64u * 528u, item_features + (size_t)s0 * 128, 64, tid);
    stage_hilo128(sm, EB_WU, upw, 64, tid);
    stage_hilo128(sm, EB_WI, ipw, 64, tid);
    __syncthreads();

    float acc[8][4];
    #pragma unroll
    for (int j = 0; j < 8; ++j) { acc[j][0] = acc[j][1] = acc[j][2] = acc[j][3] = 0.f; }
    gemm3<8>(acc, smem_u32(sm + EB_FEAT) + (uint32_t)(16 * w) * 528u, 528,
             smem_u32(sm + (w < 4 ? EB_WU : EB_WI)), 528);

    const int side = w >> 2;
    const int qr = lane >> 2, qc = lane & 3;
    const int r0 = 16 * w + qr;
    const int sA = side ? r0 - 64 : r0;
    const int sB = sA + 8;
    const float* bb  = side ? ipb : upb;
    const float* tbl = side ? item_table : user_table;
    const float* pep = pe + side * 64;
    size_t tA = (size_t)sidx[side * 64 + sA] * 64;
    size_t tB = (size_t)sidx[side * 64 + sB] * 64;
    float* dA = g_x0 + ((size_t)(s0 + sA) * 2 + side) * 64;
    float* dB = g_x0 + ((size_t)(s0 + sB) * 2 + side) * 64;
    #pragma unroll
    for (int j = 0; j < 8; ++j) {
        int c = 8 * j + 2 * qc;
        dA[c]     = acc[j][0] + __ldg(bb + c)     + __ldg(tbl + tA + c)     + __ldg(pep + c);
        dA[c + 1] = acc[j][1] + __ldg(bb + c + 1) + __ldg(tbl + tA + c + 1) + __ldg(pep + c + 1);
        dB[c]     = acc[j][2] + __ldg(bb + c)     + __ldg(tbl + tB + c)     + __ldg(pep + c);
        dB[c + 1] = acc[j][3] + __ldg(bb + c + 1) + __ldg(tbl + tB + c + 1) + __ldg(pep + c + 1);
    }
}

// =====================================================================================
// Main kernel: 256 threads, 64 samples (128 token rows), register-resident activations.
// smem: XT head tile [64][528B] @0 | WB ring 2x52224 @33792   total 138240
// 13 sync phases: per layer {qkv, out, ff0..ff3}, then head.
// =====================================================================================
#define XT_OFF 0u
#define WB_OFF 33792u
#define MAIN_SMEM 138240u
#define MT 256

#define CP16(dst, src) asm volatile("cp.async.cg.shared.global [%0], [%1], 16;" \
                                    :: "r"(dst), "l"(src) : "memory")
#define CP_COMMIT() asm volatile("cp.async.commit_group;" ::: "memory")
#define CP_WAIT0()  asm volatile("cp.async.wait_group 0;" ::: "memory")

static __device__ __forceinline__ void stage_cp(uint32_t dst, const unsigned char* src,
                                                int bytes, int tid) {
    for (int o = tid * 16; o < bytes; o += MT * 16)
        CP16(dst + o, src + o);
}

static __device__ __forceinline__ void phase_src(int p, int& off, int& bytes) {
    if (p == 12) { off = 24 * 17408; bytes = 33792; return; }
    int l = p / 6, k = p % 6;
    int ch = l * 12 + (k == 0 ? 0 : (k == 1 ? 3 : 4 + 2 * (k - 2)));
    off = ch * 17408;
    bytes = (k == 0 ? 52224 : (k == 1 ? 17408 : 34816));
}

// register-only LayerNorm over one 64-wide row spread across 4 qc lanes
static __device__ __forceinline__ void ln_reg(float v[8][2], const float* g, const float* b, int qc) {
    float s = 0.f;
    #pragma unroll
    for (int j = 0; j < 8; ++j) s += v[j][0] + v[j][1];
    s += __shfl_xor_sync(0xffffffffu, s, 1);
    s += __shfl_xor_sync(0xffffffffu, s, 2);
    float m = s * (1.f / 64.f);
    float var = 0.f;
    #pragma unroll
    for (int j = 0; j < 8; ++j) {
        float d0 = v[j][0] - m, d1 = v[j][1] - m;
        var += d0 * d0 + d1 * d1;
    }
    var += __shfl_xor_sync(0xffffffffu, var, 1);
    var += __shfl_xor_sync(0xffffffffu, var, 2);
    float inv = rsqrtf(var * (1.f / 64.f) + 1e-5f);
    #pragma unroll
    for (int j = 0; j < 8; ++j) {
        int cc = 8 * j + 2 * qc;
        v[j][0] = (v[j][0] - m) * inv * __ldg(g + cc)     + __ldg(b + cc);
        v[j][1] = (v[j][1] - m) * inv * __ldg(g + cc + 1) + __ldg(b + cc + 1);
    }
}

__global__ void __launch_bounds__(MT, 1)
main_kernel(const float* __restrict__ in_b, const float* __restrict__ out_b,
            const float* __restrict__ ln1_g, const float* __restrict__ ln1_b,
            const float* __restrict__ ff1_b, const float* __restrict__ ff2_b,
            const float* __restrict__ ln2_g, const float* __restrict__ ln2_b,
            const float* __restrict__ h1_b, const float* __restrict__ h2_w,
            const float* __restrict__ h2_b, float* __restrict__ out)
{
    extern __shared__ char sm[];
    const int tid = threadIdx.x, lane = tid & 31, w = tid >> 5;
    const int qr = lane >> 2, qc = lane & 3;
    const int rA = 16 * w + qr;               // token rows owned: rA, rA+8
    const int s0m = blockIdx.x << 6;
    const uint32_t xt_u = smem_u32(sm + XT_OFF);
    const uint32_t wb_u = smem_u32(sm + WB_OFF);
    const uint32_t slot[2] = { wb_u, wb_u + 52224u };

    // prefetch phase 0 immediately
    stage_cp(slot[0], g_wbuf, 52224, tid);
    CP_COMMIT();

    // x0 -> registers
    float x_[2][8][2];
    {
        const float* x0p = g_x0 + (size_t)(blockIdx.x * 128) * 64;
        #pragma unroll
        for (int h = 0; h < 2; ++h) {
            const float* xp = x0p + (size_t)(rA + 8 * h) * 64;
            #pragma unroll
            for (int j = 0; j < 8; ++j) {
                float2 f = __ldg(reinterpret_cast<const float2*>(xp + 8 * j + 2 * qc));
                x_[h][j][0] = f.x; x_[h][j][1] = f.y;
            }
        }
    }

    uint32_t fxh[4][4], fxl[4][4];            // current x fragments
    build_fr(x_, fxh, fxl);

    float wS[2][4], wO[2][4];
    float accF[8][4];
    uint32_t fch[4][4], fcl[4][4];            // ctx / hidden fragments (reused)
    int pid = 0;

    for (int l = 0; l < 2; ++l) {
        for (int k = 0; k < 6; ++k) {
            CP_WAIT0();
            __syncthreads();
            if (pid < 12) {
                int off, by; phase_src(pid + 1, off, by);
                stage_cp(slot[(pid + 1) & 1], g_wbuf + off, by, tid);
                CP_COMMIT();
            }
            const uint32_t bb = slot[pid & 1];

            if (k == 0) {
                // ======== qkv + attention (one phase) ========
                float q_[8][4];
                #pragma unroll
                for (int j = 0; j < 8; ++j) { q_[j][0] = q_[j][1] = q_[j][2] = q_[j][3] = 0.f; }
                gemm3r(q_, fxh, fxl, bb);
                const float* bq = in_b + l * 192;
                #pragma unroll
                for (int j = 0; j < 8; ++j) {
                    int c = 8 * j + 2 * qc;
                    float b0 = __ldg(bq + c), b1 = __ldg(bq + c + 1);
                    q_[j][0] += b0; q_[j][1] += b1; q_[j][2] += b0; q_[j][3] += b1;
                }

                float acc[8][4];
                #pragma unroll
                for (int j = 0; j < 8; ++j) { acc[j][0] = acc[j][1] = acc[j][2] = acc[j][3] = 0.f; }
                gemm3r(acc, fxh, fxl, bb + 17408u);
                const float* bk = in_b + l * 192 + 64;
                #pragma unroll
                for (int j = 0; j < 8; ++j) {
                    int c = 8 * j + 2 * qc;
                    float b0 = __ldg(bk + c), b1 = __ldg(bk + c + 1);
                    acc[j][0] += b0; acc[j][1] += b1; acc[j][2] += b0; acc[j][3] += b1;
                }
                // scores + softmax
                {
                    float sS[2][4], sO[2][4];
                    #pragma unroll
                    for (int h = 0; h < 4; ++h) {
                        int j0 = 2 * h, j1 = 2 * h + 1;
                        sS[0][h] = q_[j0][0] * acc[j0][0] + q_[j0][1] * acc[j0][1]
                                 + q_[j1][0] * acc[j1][0] + q_[j1][1] * acc[j1][1];
                        sS[1][h] = q_[j0][2] * acc[j0][2] + q_[j0][3] * acc[j0][3]
                                 + q_[j1][2] * acc[j1][2] + q_[j1][3] * acc[j1][3];
                        float k00 = __shfl_xor_sync(0xffffffffu, acc[j0][0], 4);
                        float k01 = __shfl_xor_sync(0xffffffffu, acc[j0][1], 4);
                        float k10 = __shfl_xor_sync(0xffffffffu, acc[j1][0], 4);
                        float k11 = __shfl_xor_sync(0xffffffffu, acc[j1][1], 4);
                        float k02 = __shfl_xor_sync(0xffffffffu, acc[j0][2], 4);
                        float k03 = __shfl_xor_sync(0xffffffffu, acc[j0][3], 4);
                        float k12 = __shfl_xor_sync(0xffffffffu, acc[j1][2], 4);
                        float k13 = __shfl_xor_sync(0xffffffffu, acc[j1][3], 4);
                        sO[0][h] = q_[j0][0] * k00 + q_[j0][1] * k01 + q_[j1][0] * k10 + q_[j1][1] * k11;
                        sO[1][h] = q_[j0][2] * k02 + q_[j0][3] * k03 + q_[j1][2] * k12 + q_[j1][3] * k13;
                    }
                    #pragma unroll
                    for (int r = 0; r < 2; ++r)
                        #pragma unroll
                        for (int h = 0; h < 4; ++h) {
                            sS[r][h] += __shfl_xor_sync(0xffffffffu, sS[r][h], 1);
                            sS[r][h] += __shfl_xor_sync(0xffffffffu, sS[r][h], 2);
                            sO[r][h] += __shfl_xor_sync(0xffffffffu, sO[r][h], 1);
                            sO[r][h] += __shfl_xor_sync(0xffffffffu, sO[r][h], 2);
                            float a = sS[r][h] * 0.25f, o = sO[r][h] * 0.25f;
                            float m = fmaxf(a, o);
                            float ea = __expf(a - m), eo = __expf(o - m);
                            float inv = __fdividef(1.f, ea + eo);
                            wS[r][h] = ea * inv; wO[r][h] = eo * inv;
                        }
                }
                // v
                #pragma unroll
                for (int j = 0; j < 8; ++j) { acc[j][0] = acc[j][1] = acc[j][2] = acc[j][3] = 0.f; }
                gemm3r(acc, fxh, fxl, bb + 34816u);
                const float* bv = in_b + l * 192 + 128;
                #pragma unroll
                for (int j = 0; j < 8; ++j) {
                    int c = 8 * j + 2 * qc;
                    float b0 = __ldg(bv + c), b1 = __ldg(bv + c + 1);
                    acc[j][0] += b0; acc[j][1] += b1; acc[j][2] += b0; acc[j][3] += b1;
                }
                // ctx -> fragments (registers only)
                #pragma unroll
                for (int j = 0; j < 8; ++j) {
                    int h = j >> 1;
                    float p0 = __shfl_xor_sync(0xffffffffu, acc[j][0], 4);
                    float p1 = __shfl_xor_sync(0xffffffffu, acc[j][1], 4);
                    float p2 = __shfl_xor_sync(0xffffffffu, acc[j][2], 4);
                    float p3 = __shfl_xor_sync(0xffffffffu, acc[j][3], 4);
                    float c00 = wS[0][h] * acc[j][0] + wO[0][h] * p0;
                    float c01 = wS[0][h] * acc[j][1] + wO[0][h] * p1;
                    float c10 = wS[1][h] * acc[j][2] + wO[1][h] * p2;
                    float c11 = wS[1][h] * acc[j][3] + wO[1][h] * p3;
                    int kc = j >> 1, jh = j & 1;
                    cvt_pair(c00, c01, fch[kc][(jh << 1) | 0], fcl[kc][(jh << 1) | 0]);
                    cvt_pair(c10, c11, fch[kc][(jh << 1) | 1], fcl[kc][(jh << 1) | 1]);
                }
            } else if (k == 1) {
                // ======== out-proj + residual + LN1 ========
                float acc[8][4];
                #pragma unroll
                for (int j = 0; j < 8; ++j) { acc[j][0] = acc[j][1] = acc[j][2] = acc[j][3] = 0.f; }
                gemm3r(acc, fch, fcl, bb);
                const float* bo = out_b + l * 64;
                #pragma unroll
                for (int j = 0; j < 8; ++j) {
                    int c = 8 * j + 2 * qc;
                    float b0 = __ldg(bo + c), b1 = __ldg(bo + c + 1);
                    x_[0][j][0] += acc[j][0] + b0; x_[0][j][1] += acc[j][1] + b1;
                    x_[1][j][0] += acc[j][2] + b0; x_[1][j][1] += acc[j][3] + b1;
                }
                ln_reg(x_[0], ln1_g + l * 64, ln1_b + l * 64, qc);
                ln_reg(x_[1], ln1_g + l * 64, ln1_b + l * 64, qc);
                build_fr(x_, fxh, fxl);
            } else {
                // ======== ff pair: ff1 chunk -> relu -> ff2 chunk ========
                int c4 = k - 2;
                float acc[8][4];
                #pragma unroll
                for (int j = 0; j < 8; ++j) { acc[j][0] = acc[j][1] = acc[j][2] = acc[j][3] = 0.f; }
                gemm3r(acc, fxh, fxl, bb);
                const float* b1p = ff1_b + l * 256 + 64 * c4;
                #pragma unroll
                for (int j = 0; j < 8; ++j) {
                    int c = 8 * j + 2 * qc;
                    float b0 = __ldg(b1p + c), b1 = __ldg(b1p + c + 1);
                    float h00 = fmaxf(acc[j][0] + b0, 0.f), h01 = fmaxf(acc[j][1] + b1, 0.f);
                    float h10 = fmaxf(acc[j][2] + b0, 0.f), h11 = fmaxf(acc[j][3] + b1, 0.f);
                    int kc = j >> 1, jh = j & 1;
                    cvt_pair(h00, h01, fch[kc][(jh << 1) | 0], fcl[kc][(jh << 1) | 0]);
                    cvt_pair(h10, h11, fch[kc][(jh << 1) | 1], fcl[kc][(jh << 1) | 1]);
                }
                if (c4 == 0) {
                    #pragma unroll
                    for (int j = 0; j < 8; ++j) { accF[j][0] = accF[j][1] = accF[j][2] = accF[j][3] = 0.f; }
                }
                gemm3r(accF, fch, fcl, bb + 17408u);
                if (c4 == 3) {
                    const float* b2 = ff2_b + l * 64;
                    #pragma unroll
                    for (int j = 0; j < 8; ++j) {
                        int c = 8 * j + 2 * qc;
                        float b0 = __ldg(b2 + c), b1 = __ldg(b2 + c + 1);
                        x_[0][j][0] += accF[j][0] + b0; x_[0][j][1] += accF[j][1] + b1;
                        x_[1][j][0] += accF[j][2] + b0; x_[1][j][1] += accF[j][3] + b1;
                    }
                    ln_reg(x_[0], ln2_g + l * 64, ln2_b + l * 64, qc);
                    ln_reg(x_[1], ln2_g + l * 64, ln2_b + l * 64, qc);
                    if (l == 0) {
                        build_fr(x_, fxh, fxl);
                    } else {
                        // write head A tile: row = sample, cols = 64*(token&1) + c
                        #pragma unroll
                        for (int h = 0; h < 2; ++h) {
                            int row = (rA + 8 * h) >> 1;
                            int cb  = 64 * ((rA + 8 * h) & 1);
                            #pragma unroll
                            for (int j = 0; j < 8; ++j) {
                                int c = 8 * j + 2 * qc;
                                st_hilo(sm, XT_OFF, 264, row, cb + c, 128,
                                        x_[h][j][0], x_[h][j][1]);
                            }
                        }
                    }
                }
            }
            ++pid;
        }
    }

    // ================= head =================
    CP_WAIT0();
    __syncthreads();                        // head weights in slot[0]; XT tile visible

    if (w < 4) {
        float acc[8][4];
        #pragma unroll
        for (int j = 0; j < 8; ++j) { acc[j][0] = acc[j][1] = acc[j][2] = acc[j][3] = 0.f; }
        gemm3<8>(acc, xt_u + (uint32_t)(16 * w) * 528u, 528, slot[0], 528);
        float pA = 0.f, pB = 0.f;
        #pragma unroll
        for (int j = 0; j < 8; ++j) {
            int c = 8 * j + 2 * qc;
            float b0 = __ldg(h1_b + c), b1 = __ldg(h1_b + c + 1);
            float w0 = __ldg(h2_w + c), w1 = __ldg(h2_w + c + 1);
            pA += fmaxf(acc[j][0] + b0, 0.f) * w0 + fmaxf(acc[j][1] + b1, 0.f) * w1;
            pB += fmaxf(acc[j][2] + b0, 0.f) * w0 + fmaxf(acc[j][3] + b1, 0.f) * w1;
        }
        pA += __shfl_xor_sync(0xffffffffu, pA, 1);
        pA += __shfl_xor_sync(0xffffffffu, pA, 2);
        pB += __shfl_xor_sync(0xffffffffu, pB, 1);
        pB += __shfl_xor_sync(0xffffffffu, pB, 2);
        if (qc == 0) {
            float hb = __ldg(h2_b);
            out[s0m + 16 * w + qr]     = pA + hb;
            out[s0m + 16 * w + qr + 8] = pB + hb;
        }
    }
}

// =====================================================================================
extern "C" void kernel_launch(void* const* d_in, const int* in_sizes, int n_in,
                              void* d_out, int out_size)
{
    const int*   user_idx      = (const int*)  d_in[0];
    const int*   item_idx      = (const int*)  d_in[1];
    const float* user_features = (const float*)d_in[2];
    const float* item_features = (const float*)d_in[3];
    const float* user_table    = (const float*)d_in[4];
    const float* item_table    = (const float*)d_in[5];
    const float* upw           = (const float*)d_in[6];
    const float* upb           = (const float*)d_in[7];
    const float* ipw           = (const float*)d_in[8];
    const float* ipb           = (const float*)d_in[9];
    const float* pe            = (const float*)d_in[10];
    const float* in_w          = (const float*)d_in[11];
    const float* in_b          = (const float*)d_in[12];
    const float* out_w         = (const float*)d_in[13];
    const float* out_b         = (const float*)d_in[14];
    const float* ln1_g         = (const float*)d_in[15];
    const float* ln1_b         = (const float*)d_in[16];
    const float* ff1_w         = (const float*)d_in[17];
    const float* ff1_b         = (const float*)d_in[18];
    const float* ff2_w         = (const float*)d_in[19];
    const float* ff2_b         = (const float*)d_in[20];
    const float* ln2_g         = (const float*)d_in[21];
    const float* ln2_b         = (const float*)d_in[22];
    const float* h1_w          = (const float*)d_in[23];
    const float* h1_b          = (const float*)d_in[24];
    const float* h2_w          = (const float*)d_in[25];
    const float* h2_b          = (const float*)d_in[26];
    float* out = (float*)d_out;

    const int B = in_sizes[0];

    static bool attr_set = false;
    if (!attr_set) {
        cudaFuncSetAttribute(pre_kernel,  cudaFuncAttributeMaxDynamicSharedMemorySize, EB_SMEM);
        cudaFuncSetAttribute(main_kernel, cudaFuncAttributeMaxDynamicSharedMemorySize, MAIN_SMEM);
        attr_set = true;
    }

    pre_kernel<<<25 + B / 64, 256, EB_SMEM>>>(user_idx, item_idx, user_features, item_features,
                                              user_table, item_table, upw, upb, ipw, ipb, pe,
                                              in_w, out_w, ff1_w, ff2_w, h1_w);
    main_kernel<<<B / 64, MT, MAIN_SMEM>>>(in_b, out_b, ln1_g, ln1_b, ff1_b, ff2_b,
                                           ln2_g, ln2_b, h1_b, h2_w, h2_b, out);
}

// round 8
// speedup vs baseline: 1.5505x; 1.4843x over previous
#include <cuda_runtime.h>
#include <cuda_bf16.h>
#include <cstdint>

#define MAXB 131072

// ---------------- persistent device scratch (no runtime allocation) ----------------
// layout: 24 x 17408 (64x64 K-chunk images) | h1 image 33792 | upw image 33792 | ipw image 33792
__device__ __align__(16) float          g_x0[(size_t)MAXB * 2 * 64];
__device__ __align__(16) unsigned char  g_wbuf[24 * 17408 + 3 * 33792];
#define WOFF_H1  (24 * 17408)
#define WOFF_UPW (WOFF_H1 + 33792)
#define WOFF_IPW (WOFF_UPW + 33792)

// ---------------- common helpers ----------------
static __device__ __forceinline__ uint32_t smem_u32(const void* p) {
    uint32_t a;
    asm("{ .reg .u64 t; cvta.to.shared.u64 t, %1; cvt.u32.u64 %0, t; }" : "=r"(a) : "l"(p));
    return a;
}
static __device__ __forceinline__ void ldmA(uint32_t a[4], uint32_t addr) {
    asm volatile("ldmatrix.sync.aligned.m8n8.x4.shared.b16 {%0,%1,%2,%3}, [%4];"
                 : "=r"(a[0]), "=r"(a[1]), "=r"(a[2]), "=r"(a[3]) : "r"(addr));
}
static __device__ __forceinline__ void ldmB4(uint32_t b[4], uint32_t addr) {
    asm volatile("ldmatrix.sync.aligned.m8n8.x4.shared.b16 {%0,%1,%2,%3}, [%4];"
                 : "=r"(b[0]), "=r"(b[1]), "=r"(b[2]), "=r"(b[3]) : "r"(addr));
}
static __device__ __forceinline__ void mma16816(float d[4], const uint32_t a[4], const uint32_t b[2]) {
    asm volatile("mma.sync.aligned.m16n8k16.row.col.f32.bf16.bf16.f32 "
                 "{%0,%1,%2,%3}, {%4,%5,%6,%7}, {%8,%9}, {%0,%1,%2,%3};"
                 : "+f"(d[0]), "+f"(d[1]), "+f"(d[2]), "+f"(d[3])
                 : "r"(a[0]), "r"(a[1]), "r"(a[2]), "r"(a[3]), "r"(b[0]), "r"(b[1]));
}

// register-A 3-term gemm with x4 B loads. B tile [64 rows][BSTR bytes], lo block at +KLO.
// x4 address: lanes 0-15 -> n-block 2jp, lanes 16-31 -> n-block 2jp+1 (baked into bAddr).
template<int NKC, int BSTR, int KLO>
static __device__ __forceinline__ void gemm3r4(float (*acc)[4],
        const uint32_t (*fh)[4], const uint32_t (*fl)[4], uint32_t bBase) {
    const int lane = threadIdx.x & 31;
    uint32_t bAddr = bBase + (lane & 7) * BSTR + (((lane >> 3) & 1) << 4)
                   + ((lane >> 4) & 1) * 8 * BSTR;
    #pragma unroll
    for (int kc = 0; kc < NKC; ++kc) {
        uint32_t bh[4][4];
        #pragma unroll
        for (int jp = 0; jp < 4; ++jp)
            ldmB4(bh[jp], bAddr + jp * 16 * BSTR + kc * 32);
        #pragma unroll
        for (int jp = 0; jp < 4; ++jp) {
            mma16816(acc[2 * jp],     fh[kc], &bh[jp][0]);
            mma16816(acc[2 * jp + 1], fh[kc], &bh[jp][2]);
        }
        #pragma unroll
        for (int jp = 0; jp < 4; ++jp) {
            mma16816(acc[2 * jp],     fl[kc], &bh[jp][0]);
            mma16816(acc[2 * jp + 1], fl[kc], &bh[jp][2]);
        }
        #pragma unroll
        for (int jp = 0; jp < 4; ++jp) {
            uint32_t bl[4];
            ldmB4(bl, bAddr + jp * 16 * BSTR + kc * 32 + KLO);
            mma16816(acc[2 * jp],     fh[kc], &bl[0]);
            mma16816(acc[2 * jp + 1], fh[kc], &bl[2]);
        }
    }
}

// tile-A 3-term gemm with x4 B loads (head only). A tile lo block at +NKC*32 bytes.
template<int NKC, int BSTR, int KLO>
static __device__ void gemm3t(float (*acc)[4], uint32_t aBase, int aStrB, uint32_t bBase) {
    const int lane = threadIdx.x & 31;
    const int KB = NKC * 32;
    uint32_t aAddr = aBase + (lane & 15) * aStrB + ((lane >> 4) << 4);
    uint32_t bAddr = bBase + (lane & 7) * BSTR + (((lane >> 3) & 1) << 4)
                   + ((lane >> 4) & 1) * 8 * BSTR;
    #pragma unroll
    for (int kc = 0; kc < NKC; ++kc) {
        uint32_t ah[4], al[4];
        ldmA(ah, aAddr + kc * 32);
        ldmA(al, aAddr + kc * 32 + KB);
        uint32_t bh[4][4];
        #pragma unroll
        for (int jp = 0; jp < 4; ++jp)
            ldmB4(bh[jp], bAddr + jp * 16 * BSTR + kc * 32);
        #pragma unroll
        for (int jp = 0; jp < 4; ++jp) {
            mma16816(acc[2 * jp],     ah, &bh[jp][0]);
            mma16816(acc[2 * jp + 1], ah, &bh[jp][2]);
        }
        #pragma unroll
        for (int jp = 0; jp < 4; ++jp) {
            mma16816(acc[2 * jp],     al, &bh[jp][0]);
            mma16816(acc[2 * jp + 1], al, &bh[jp][2]);
        }
        #pragma unroll
        for (int jp = 0; jp < 4; ++jp) {
            uint32_t bl[4];
            ldmB4(bl, bAddr + jp * 16 * BSTR + kc * 32 + KLO);
            mma16816(acc[2 * jp],     ah, &bl[0]);
            mma16816(acc[2 * jp + 1], ah, &bl[2]);
        }
    }
}

// convert fp32 pair -> packed bf16 hi + packed bf16 lo
static __device__ __forceinline__ void cvt_pair(float v0, float v1, uint32_t& h, uint32_t& l) {
    __nv_bfloat162 hb = __floats2bfloat162_rn(v0, v1);
    h = *reinterpret_cast<uint32_t*>(&hb);
    float r0 = v0 - __bfloat162float(hb.x);
    float r1 = v1 - __bfloat162float(hb.y);
    __nv_bfloat162 lb = __floats2bfloat162_rn(r0, r1);
    l = *reinterpret_cast<uint32_t*>(&lb);
}

// build m16n8k16 A fragments (hi+lo) from register values v[rowhalf][j][2]
static __device__ __forceinline__ void build_fr(const float v[2][8][2],
                                                uint32_t fh[4][4], uint32_t fl[4][4]) {
    #pragma unroll
    for (int kc = 0; kc < 4; ++kc)
        #pragma unroll
        for (int m = 0; m < 4; ++m) {
            int h = m & 1, j = 2 * kc + (m >> 1);
            cvt_pair(v[h][j][0], v[h][j][1], fh[kc][m], fl[kc][m]);
        }
}

// hi/lo bf16 pair store into padded tile [r][strideElems], hi cols 0:K, lo K:2K
static __device__ __forceinline__ void st_hilo(char* sm, uint32_t off, int strideElems,
                                               int r, int c, int K, float f0, float f1) {
    uint32_t hh, ll;
    cvt_pair(f0, f1, hh, ll);
    __nv_bfloat16* row = (__nv_bfloat16*)(sm + off) + (size_t)r * strideElems;
    *reinterpret_cast<uint32_t*>(row + c)     = hh;
    *reinterpret_cast<uint32_t*>(row + K + c) = ll;
}

// ---------------- cp.async ----------------
#define CP16(dst, src) asm volatile("cp.async.cg.shared.global [%0], [%1], 16;" \
                                    :: "r"(dst), "l"(src) : "memory")
#define CP_COMMIT() asm volatile("cp.async.commit_group;" ::: "memory")
#define CP_WAIT0()  asm volatile("cp.async.wait_group 0;" ::: "memory")

static __device__ __forceinline__ void stage_cp(uint32_t dst, const unsigned char* src,
                                                int bytes, int tid) {
    for (int o = tid * 16; o < bytes; o += 256 * 16)
        CP16(dst + o, src + o);
}

// =====================================================================================
// Kernel 1: convert all weights to hi/lo tile images (27 blocks)
// =====================================================================================
__global__ void conv_w_kernel(const float* __restrict__ in_w, const float* __restrict__ out_w,
                              const float* __restrict__ ff1_w, const float* __restrict__ ff2_w,
                              const float* __restrict__ h1_w, const float* __restrict__ upw,
                              const float* __restrict__ ipw)
{
    int b = blockIdx.x;
    if (b < 24) {
        int l = b / 12, c = b % 12;
        const float* src; int rs;
        if (c < 3)       { src = in_w  + ((size_t)l * 192 + 64 * c) * 64; rs = 64; }
        else if (c == 3) { src = out_w + (size_t)l * 4096;                rs = 64; }
        else {
            int cc = (c - 4) >> 1;
            if (((c - 4) & 1) == 0) { src = ff1_w + ((size_t)l * 256 + 64 * cc) * 64; rs = 64;  }
            else                    { src = ff2_w + (size_t)l * 16384 + 64 * cc;      rs = 256; }
        }
        unsigned char* dst = g_wbuf + (size_t)b * 17408;
        for (int idx = threadIdx.x; idx < 64 * 32; idx += 256) {
            int n = idx >> 5, k2 = (idx & 31) << 1;
            float2 f = *reinterpret_cast<const float2*>(src + (size_t)n * rs + k2);
            uint32_t hh, ll;
            cvt_pair(f.x, f.y, hh, ll);
            *reinterpret_cast<uint32_t*>(dst + n * 272 + k2 * 2)       = hh;
            *reinterpret_cast<uint32_t*>(dst + n * 272 + 128 + k2 * 2) = ll;
        }
    } else {
        const float* src = (b == 24) ? h1_w : (b == 25 ? upw : ipw);
        unsigned char* dst = g_wbuf + WOFF_H1 + (size_t)(b - 24) * 33792;
        for (int idx = threadIdx.x; idx < 64 * 64; idx += 256) {
            int n = idx >> 6, k2 = (idx & 63) << 1;
            float2 f = *reinterpret_cast<const float2*>(src + (size_t)n * 128 + k2);
            uint32_t hh, ll;
            cvt_pair(f.x, f.y, hh, ll);
            *reinterpret_cast<uint32_t*>(dst + n * 528 + k2 * 2)       = hh;
            *reinterpret_cast<uint32_t*>(dst + n * 528 + 256 + k2 * 2) = ll;
        }
    }
}

// =====================================================================================
// Kernel 2: embedding. Features -> register A-fragments (no smem staging);
// weights cp.async'd preconverted. smem 67584 -> 2 CTAs/SM.
// =====================================================================================
#define EB_SMEM 67584u

__global__ void __launch_bounds__(256, 2)
embed_kernel(const int* __restrict__ user_idx, const int* __restrict__ item_idx,
             const float* __restrict__ user_features, const float* __restrict__ item_features,
             const float* __restrict__ user_table, const float* __restrict__ item_table,
             const float* __restrict__ upb, const float* __restrict__ ipb,
             const float* __restrict__ pe)
{
    extern __shared__ char sm[];
    const int tid = threadIdx.x, lane = tid & 31, w = tid >> 5;
    const int qr = lane >> 2, qc = lane & 3;
    const int s0 = blockIdx.x << 6;

    // stage both weight images (upw | ipw, contiguous) via cp.async
    stage_cp(smem_u32(sm), g_wbuf + WOFF_UPW, 67584, tid);
    CP_COMMIT();

    const int side = w >> 2;
    const int r0 = 16 * w + qr;
    const int sA = side ? r0 - 64 : r0;
    const int sB = sA + 8;
    const float* featp = side ? item_features : user_features;
    const float* fpA = featp + (size_t)(s0 + sA) * 128;
    const float* fpB = featp + (size_t)(s0 + sB) * 128;

    // features -> K=128 A fragments in registers (coalesced LDG.64, overlapped with cp.async)
    uint32_t fh[8][4], fl[8][4];
    #pragma unroll
    for (int kc = 0; kc < 8; ++kc)
        #pragma unroll
        for (int m = 0; m < 4; ++m) {
            const float* p = (m & 1) ? fpB : fpA;
            int col = 16 * kc + 8 * (m >> 1) + 2 * qc;
            float2 f = __ldg(reinterpret_cast<const float2*>(p + col));
            cvt_pair(f.x, f.y, fh[kc][m], fl[kc][m]);
        }

    int myIdxA = side ? __ldg(item_idx + s0 + sA) : __ldg(user_idx + s0 + sA);
    int myIdxB = side ? __ldg(item_idx + s0 + sB) : __ldg(user_idx + s0 + sB);

    CP_WAIT0();
    __syncthreads();

    float acc[8][4];
    #pragma unroll
    for (int j = 0; j < 8; ++j) { acc[j][0] = acc[j][1] = acc[j][2] = acc[j][3] = 0.f; }
    gemm3r4<8, 528, 256>(acc, fh, fl, smem_u32(sm) + (side ? 33792u : 0u));

    const float* bb  = side ? ipb : upb;
    const float* tbl = side ? item_table : user_table;
    const float* pep = pe + side * 64;
    size_t tA = (size_t)myIdxA * 64;
    size_t tB = (size_t)myIdxB * 64;
    float* dA = g_x0 + ((size_t)(s0 + sA) * 2 + side) * 64;
    float* dB = g_x0 + ((size_t)(s0 + sB) * 2 + side) * 64;
    #pragma unroll
    for (int j = 0; j < 8; ++j) {
        int c = 8 * j + 2 * qc;
        dA[c]     = acc[j][0] + __ldg(bb + c)     + __ldg(tbl + tA + c)     + __ldg(pep + c);
        dA[c + 1] = acc[j][1] + __ldg(bb + c + 1) + __ldg(tbl + tA + c + 1) + __ldg(pep + c + 1);
        dB[c]     = acc[j][2] + __ldg(bb + c)     + __ldg(tbl + tB + c)     + __ldg(pep + c);
        dB[c + 1] = acc[j][3] + __ldg(bb + c + 1) + __ldg(tbl + tB + c + 1) + __ldg(pep + c + 1);
    }
}

// =====================================================================================
// Kernel 3: main transformer. 256 threads, 64 samples, register-resident activations.
// smem: XT head tile [64][528B] @0 | WB ring 2x52224 @33792   total 138240
// =====================================================================================
#define XT_OFF 0u
#define WB_OFF 33792u
#define MAIN_SMEM 138240u
#define MT 256

static __device__ __forceinline__ void phase_src(int p, int& off, int& bytes) {
    if (p == 12) { off = WOFF_H1; bytes = 33792; return; }
    int l = p / 6, k = p % 6;
    int ch = l * 12 + (k == 0 ? 0 : (k == 1 ? 3 : 4 + 2 * (k - 2)));
    off = ch * 17408;
    bytes = (k == 0 ? 52224 : (k == 1 ? 17408 : 34816));
}

// register-only LayerNorm over one 64-wide row spread across 4 qc lanes
static __device__ __forceinline__ void ln_reg(float v[8][2], const float* g, const float* b, int qc) {
    float s = 0.f;
    #pragma unroll
    for (int j = 0; j < 8; ++j) s += v[j][0] + v[j][1];
    s += __shfl_xor_sync(0xffffffffu, s, 1);
    s += __shfl_xor_sync(0xffffffffu, s, 2);
    float m = s * (1.f / 64.f);
    float var = 0.f;
    #pragma unroll
    for (int j = 0; j < 8; ++j) {
        float d0 = v[j][0] - m, d1 = v[j][1] - m;
        var += d0 * d0 + d1 * d1;
    }
    var += __shfl_xor_sync(0xffffffffu, var, 1);
    var += __shfl_xor_sync(0xffffffffu, var, 2);
    float inv = rsqrtf(var * (1.f / 64.f) + 1e-5f);
    #pragma unroll
    for (int j = 0; j < 8; ++j) {
        int cc = 8 * j + 2 * qc;
        v[j][0] = (v[j][0] - m) * inv * __ldg(g + cc)     + __ldg(b + cc);
        v[j][1] = (v[j][1] - m) * inv * __ldg(g + cc + 1) + __ldg(b + cc + 1);
    }
}

__global__ void __launch_bounds__(MT, 1)
main_kernel(const float* __restrict__ in_b, const float* __restrict__ out_b,
            const float* __restrict__ ln1_g, const float* __restrict__ ln1_b,
            const float* __restrict__ ff1_b, const float* __restrict__ ff2_b,
            const float* __restrict__ ln2_g, const float* __restrict__ ln2_b,
            const float* __restrict__ h1_b, const float* __restrict__ h2_w,
            const float* __restrict__ h2_b, float* __restrict__ out)
{
    extern __shared__ char sm[];
    const int tid = threadIdx.x, lane = tid & 31, w = tid >> 5;
    const int qr = lane >> 2, qc = lane & 3;
    const int rA = 16 * w + qr;
    const int s0m = blockIdx.x << 6;
    const uint32_t xt_u = smem_u32(sm + XT_OFF);
    const uint32_t wb_u = smem_u32(sm + WB_OFF);
    const uint32_t slot[2] = { wb_u, wb_u + 52224u };

    stage_cp(slot[0], g_wbuf, 52224, tid);
    CP_COMMIT();

    float x_[2][8][2];
    {
        const float* x0p = g_x0 + (size_t)(blockIdx.x * 128) * 64;
        #pragma unroll
        for (int h = 0; h < 2; ++h) {
            const float* xp = x0p + (size_t)(rA + 8 * h) * 64;
            #pragma unroll
            for (int j = 0; j < 8; ++j) {
                float2 f = __ldg(reinterpret_cast<const float2*>(xp + 8 * j + 2 * qc));
                x_[h][j][0] = f.x; x_[h][j][1] = f.y;
            }
        }
    }

    uint32_t fxh[4][4], fxl[4][4];
    build_fr(x_, fxh, fxl);

    float wS[2][4], wO[2][4];
    float accF[8][4];
    uint32_t fch[4][4], fcl[4][4];
    int pid = 0;

    for (int l = 0; l < 2; ++l) {
        for (int k = 0; k < 6; ++k) {
            CP_WAIT0();
            __syncthreads();
            if (pid < 12) {
                int off, by; phase_src(pid + 1, off, by);
                stage_cp(slot[(pid + 1) & 1], g_wbuf + off, by, tid);
                CP_COMMIT();
            }
            const uint32_t bb = slot[pid & 1];

            if (k == 0) {
                // ======== qkv + attention ========
                float q_[8][4];
                #pragma unroll
                for (int j = 0; j < 8; ++j) { q_[j][0] = q_[j][1] = q_[j][2] = q_[j][3] = 0.f; }
                gemm3r4<4, 272, 128>(q_, fxh, fxl, bb);
                const float* bq = in_b + l * 192;
                #pragma unroll
                for (int j = 0; j < 8; ++j) {
                    int c = 8 * j + 2 * qc;
                    float b0 = __ldg(bq + c), b1 = __ldg(bq + c + 1);
                    q_[j][0] += b0; q_[j][1] += b1; q_[j][2] += b0; q_[j][3] += b1;
                }

                float acc[8][4];
                #pragma unroll
                for (int j = 0; j < 8; ++j) { acc[j][0] = acc[j][1] = acc[j][2] = acc[j][3] = 0.f; }
                gemm3r4<4, 272, 128>(acc, fxh, fxl, bb + 17408u);
                const float* bk = in_b + l * 192 + 64;
                #pragma unroll
                for (int j = 0; j < 8; ++j) {
                    int c = 8 * j + 2 * qc;
                    float b0 = __ldg(bk + c), b1 = __ldg(bk + c + 1);
                    acc[j][0] += b0; acc[j][1] += b1; acc[j][2] += b0; acc[j][3] += b1;
                }
                {
                    float sS[2][4], sO[2][4];
                    #pragma unroll
                    for (int h = 0; h < 4; ++h) {
                        int j0 = 2 * h, j1 = 2 * h + 1;
                        sS[0][h] = q_[j0][0] * acc[j0][0] + q_[j0][1] * acc[j0][1]
                                 + q_[j1][0] * acc[j1][0] + q_[j1][1] * acc[j1][1];
                        sS[1][h] = q_[j0][2] * acc[j0][2] + q_[j0][3] * acc[j0][3]
                                 + q_[j1][2] * acc[j1][2] + q_[j1][3] * acc[j1][3];
                        float k00 = __shfl_xor_sync(0xffffffffu, acc[j0][0], 4);
                        float k01 = __shfl_xor_sync(0xffffffffu, acc[j0][1], 4);
                        float k10 = __shfl_xor_sync(0xffffffffu, acc[j1][0], 4);
                        float k11 = __shfl_xor_sync(0xffffffffu, acc[j1][1], 4);
                        float k02 = __shfl_xor_sync(0xffffffffu, acc[j0][2], 4);
                        float k03 = __shfl_xor_sync(0xffffffffu, acc[j0][3], 4);
                        float k12 = __shfl_xor_sync(0xffffffffu, acc[j1][2], 4);
                        float k13 = __shfl_xor_sync(0xffffffffu, acc[j1][3], 4);
                        sO[0][h] = q_[j0][0] * k00 + q_[j0][1] * k01 + q_[j1][0] * k10 + q_[j1][1] * k11;
                        sO[1][h] = q_[j0][2] * k02 + q_[j0][3] * k03 + q_[j1][2] * k12 + q_[j1][3] * k13;
                    }
                    #pragma unroll
                    for (int r = 0; r < 2; ++r)
                        #pragma unroll
                        for (int h = 0; h < 4; ++h) {
                            sS[r][h] += __shfl_xor_sync(0xffffffffu, sS[r][h], 1);
                            sS[r][h] += __shfl_xor_sync(0xffffffffu, sS[r][h], 2);
                            sO[r][h] += __shfl_xor_sync(0xffffffffu, sO[r][h], 1);
                            sO[r][h] += __shfl_xor_sync(0xffffffffu, sO[r][h], 2);
                            float a = sS[r][h] * 0.25f, o = sO[r][h] * 0.25f;
                            float m = fmaxf(a, o);
                            float ea = __expf(a - m), eo = __expf(o - m);
                            float inv = __fdividef(1.f, ea + eo);
                            wS[r][h] = ea * inv; wO[r][h] = eo * inv;
                        }
                }
                #pragma unroll
                for (int j = 0; j < 8; ++j) { acc[j][0] = acc[j][1] = acc[j][2] = acc[j][3] = 0.f; }
                gemm3r4<4, 272, 128>(acc, fxh, fxl, bb + 34816u);
                const float* bv = in_b + l * 192 + 128;
                #pragma unroll
                for (int j = 0; j < 8; ++j) {
                    int c = 8 * j + 2 * qc;
                    float b0 = __ldg(bv + c), b1 = __ldg(bv + c + 1);
                    acc[j][0] += b0; acc[j][1] += b1; acc[j][2] += b0; acc[j][3] += b1;
                }
                #pragma unroll
                for (int j = 0; j < 8; ++j) {
                    int h = j >> 1;
                    float p0 = __shfl_xor_sync(0xffffffffu, acc[j][0], 4);
                    float p1 = __shfl_xor_sync(0xffffffffu, acc[j][1], 4);
                    float p2 = __shfl_xor_sync(0xffffffffu, acc[j][2], 4);
                    float p3 = __shfl_xor_sync(0xffffffffu, acc[j][3], 4);
                    float c00 = wS[0][h] * acc[j][0] + wO[0][h] * p0;
                    float c01 = wS[0][h] * acc[j][1] + wO[0][h] * p1;
                    float c10 = wS[1][h] * acc[j][2] + wO[1][h] * p2;
                    float c11 = wS[1][h] * acc[j][3] + wO[1][h] * p3;
                    int kc = j >> 1, jh = j & 1;
                    cvt_pair(c00, c01, fch[kc][(jh << 1) | 0], fcl[kc][(jh << 1) | 0]);
                    cvt_pair(c10, c11, fch[kc][(jh << 1) | 1], fcl[kc][(jh << 1) | 1]);
                }
            } else if (k == 1) {
                // ======== out-proj + residual + LN1 ========
                float acc[8][4];
                #pragma unroll
                for (int j = 0; j < 8; ++j) { acc[j][0] = acc[j][1] = acc[j][2] = acc[j][3] = 0.f; }
                gemm3r4<4, 272, 128>(acc, fch, fcl, bb);
                const float* bo = out_b + l * 64;
                #pragma unroll
                for (int j = 0; j < 8; ++j) {
                    int c = 8 * j + 2 * qc;
                    float b0 = __ldg(bo + c), b1 = __ldg(bo + c + 1);
                    x_[0][j][0] += acc[j][0] + b0; x_[0][j][1] += acc[j][1] + b1;
                    x_[1][j][0] += acc[j][2] + b0; x_[1][j][1] += acc[j][3] + b1;
                }
                ln_reg(x_[0], ln1_g + l * 64, ln1_b + l * 64, qc);
                ln_reg(x_[1], ln1_g + l * 64, ln1_b + l * 64, qc);
                build_fr(x_, fxh, fxl);
            } else {
                // ======== ff pair ========
                int c4 = k - 2;
                float acc[8][4];
                #pragma unroll
                for (int j = 0; j < 8; ++j) { acc[j][0] = acc[j][1] = acc[j][2] = acc[j][3] = 0.f; }
                gemm3r4<4, 272, 128>(acc, fxh, fxl, bb);
                const float* b1p = ff1_b + l * 256 + 64 * c4;
                #pragma unroll
                for (int j = 0; j < 8; ++j) {
                    int c = 8 * j + 2 * qc;
                    float b0 = __ldg(b1p + c), b1 = __ldg(b1p + c + 1);
                    float h00 = fmaxf(acc[j][0] + b0, 0.f), h01 = fmaxf(acc[j][1] + b1, 0.f);
                    float h10 = fmaxf(acc[j][2] + b0, 0.f), h11 = fmaxf(acc[j][3] + b1, 0.f);
                    int kc = j >> 1, jh = j & 1;
                    cvt_pair(h00, h01, fch[kc][(jh << 1) | 0], fcl[kc][(jh << 1) | 0]);
                    cvt_pair(h10, h11, fch[kc][(jh << 1) | 1], fcl[kc][(jh << 1) | 1]);
                }
                if (c4 == 0) {
                    #pragma unroll
                    for (int j = 0; j < 8; ++j) { accF[j][0] = accF[j][1] = accF[j][2] = accF[j][3] = 0.f; }
                }
                gemm3r4<4, 272, 128>(accF, fch, fcl, bb + 17408u);
                if (c4 == 3) {
                    const float* b2 = ff2_b + l * 64;
                    #pragma unroll
                    for (int j = 0; j < 8; ++j) {
                        int c = 8 * j + 2 * qc;
                        float b0 = __ldg(b2 + c), b1 = __ldg(b2 + c + 1);
                        x_[0][j][0] += accF[j][0] + b0; x_[0][j][1] += accF[j][1] + b1;
                        x_[1][j][0] += accF[j][2] + b0; x_[1][j][1] += accF[j][3] + b1;
                    }
                    ln_reg(x_[0], ln2_g + l * 64, ln2_b + l * 64, qc);
                    ln_reg(x_[1], ln2_g + l * 64, ln2_b + l * 64, qc);
                    if (l == 0) {
                        build_fr(x_, fxh, fxl);
                    } else {
                        #pragma unroll
                        for (int h = 0; h < 2; ++h) {
                            int row = (rA + 8 * h) >> 1;
                            int cb  = 64 * ((rA + 8 * h) & 1);
                            #pragma unroll
                            for (int j = 0; j < 8; ++j) {
                                int c = 8 * j + 2 * qc;
                                st_hilo(sm, XT_OFF, 264, row, cb + c, 128,
                                        x_[h][j][0], x_[h][j][1]);
                            }
                        }
                    }
                }
            }
            ++pid;
        }
    }

    // ================= head =================
    CP_WAIT0();
    __syncthreads();

    if (w < 4) {
        float acc[8][4];
        #pragma unroll
        for (int j = 0; j < 8; ++j) { acc[j][0] = acc[j][1] = acc[j][2] = acc[j][3] = 0.f; }
        gemm3t<8, 528, 256>(acc, xt_u + (uint32_t)(16 * w) * 528u, 528, slot[0]);
        float pA = 0.f, pB = 0.f;
        #pragma unroll
        for (int j = 0; j < 8; ++j) {
            int c = 8 * j + 2 * qc;
            float b0 = __ldg(h1_b + c), b1 = __ldg(h1_b + c + 1);
            float w0 = __ldg(h2_w + c), w1 = __ldg(h2_w + c + 1);
            pA += fmaxf(acc[j][0] + b0, 0.f) * w0 + fmaxf(acc[j][1] + b1, 0.f) * w1;
            pB += fmaxf(acc[j][2] + b0, 0.f) * w0 + fmaxf(acc[j][3] + b1, 0.f) * w1;
        }
        pA += __shfl_xor_sync(0xffffffffu, pA, 1);
        pA += __shfl_xor_sync(0xffffffffu, pA, 2);
        pB += __shfl_xor_sync(0xffffffffu, pB, 1);
        pB += __shfl_xor_sync(0xffffffffu, pB, 2);
        if (qc == 0) {
            float hb = __ldg(h2_b);
            out[s0m + 16 * w + qr]     = pA + hb;
            out[s0m + 16 * w + qr + 8] = pB + hb;
        }
    }
}

// =====================================================================================
extern "C" void kernel_launch(void* const* d_in, const int* in_sizes, int n_in,
                              void* d_out, int out_size)
{
    const int*   user_idx      = (const int*)  d_in[0];
    const int*   item_idx      = (const int*)  d_in[1];
    const float* user_features = (const float*)d_in[2];
    const float* item_features = (const float*)d_in[3];
    const float* user_table    = (const float*)d_in[4];
    const float* item_table    = (const float*)d_in[5];
    const float* upw           = (const float*)d_in[6];
    const float* upb           = (const float*)d_in[7];
    const float* ipw           = (const float*)d_in[8];
    const float* ipb           = (const float*)d_in[9];
    const float* pe            = (const float*)d_in[10];
    const float* in_w          = (const float*)d_in[11];
    const float* in_b          = (const float*)d_in[12];
    const float* out_w         = (const float*)d_in[13];
    const float* out_b         = (const float*)d_in[14];
    const float* ln1_g         = (const float*)d_in[15];
    const float* ln1_b         = (const float*)d_in[16];
    const float* ff1_w         = (const float*)d_in[17];
    const float* ff1_b         = (const float*)d_in[18];
    const float* ff2_w         = (const float*)d_in[19];
    const float* ff2_b         = (const float*)d_in[20];
    const float* ln2_g         = (const float*)d_in[21];
    const float* ln2_b         = (const float*)d_in[22];
    const float* h1_w          = (const float*)d_in[23];
    const float* h1_b          = (const float*)d_in[24];
    const float* h2_w          = (const float*)d_in[25];
    const float* h2_b          = (const float*)d_in[26];
    float* out = (float*)d_out;

    const int B = in_sizes[0];

    static bool attr_set = false;
    if (!attr_set) {
        cudaFuncSetAttribute(embed_kernel, cudaFuncAttributeMaxDynamicSharedMemorySize, EB_SMEM);
        cudaFuncSetAttribute(main_kernel,  cudaFuncAttributeMaxDynamicSharedMemorySize, MAIN_SMEM);
        attr_set = true;
    }

    conv_w_kernel<<<27, 256>>>(in_w, out_w, ff1_w, ff2_w, h1_w, upw, ipw);
    embed_kernel<<<B / 64, 256, EB_SMEM>>>(user_idx, item_idx, user_features, item_features,
                                           user_table, item_table, upb, ipb, pe);
    main_kernel<<<B / 64, MT, MAIN_SMEM>>>(in_b, out_b, ln1_g, ln1_b, ff1_b, ff2_b,
                                           ln2_g, ln2_b, h1_b, h2_w, h2_b, out);
}

// round 9
// speedup vs baseline: 1.5541x; 1.0023x over previous
#include <cuda_runtime.h>
#include <cuda_bf16.h>
#include <cstdint>

#define MAXB 131072

// ---------------- persistent device scratch (no runtime allocation) ----------------
// layout: 24 x 17408 (64x64 K-chunk images) | h1 image 33792 | upw image 33792 | ipw image 33792
__device__ __align__(16) float          g_x0[(size_t)MAXB * 2 * 64];
__device__ __align__(16) unsigned char  g_wbuf[24 * 17408 + 3 * 33792];
#define WOFF_H1  (24 * 17408)
#define WOFF_UPW (WOFF_H1 + 33792)
#define WOFF_IPW (WOFF_UPW + 33792)

// ---------------- common helpers ----------------
static __device__ __forceinline__ uint32_t smem_u32(const void* p) {
    uint32_t a;
    asm("{ .reg .u64 t; cvta.to.shared.u64 t, %1; cvt.u32.u64 %0, t; }" : "=r"(a) : "l"(p));
    return a;
}
static __device__ __forceinline__ void ldmA(uint32_t a[4], uint32_t addr) {
    asm volatile("ldmatrix.sync.aligned.m8n8.x4.shared.b16 {%0,%1,%2,%3}, [%4];"
                 : "=r"(a[0]), "=r"(a[1]), "=r"(a[2]), "=r"(a[3]) : "r"(addr));
}
static __device__ __forceinline__ void ldmB4(uint32_t b[4], uint32_t addr) {
    asm volatile("ldmatrix.sync.aligned.m8n8.x4.shared.b16 {%0,%1,%2,%3}, [%4];"
                 : "=r"(b[0]), "=r"(b[1]), "=r"(b[2]), "=r"(b[3]) : "r"(addr));
}
static __device__ __forceinline__ void mma16816(float d[4], const uint32_t a[4], const uint32_t b[2]) {
    asm volatile("mma.sync.aligned.m16n8k16.row.col.f32.bf16.bf16.f32 "
                 "{%0,%1,%2,%3}, {%4,%5,%6,%7}, {%8,%9}, {%0,%1,%2,%3};"
                 : "+f"(d[0]), "+f"(d[1]), "+f"(d[2]), "+f"(d[3])
                 : "r"(a[0]), "r"(a[1]), "r"(a[2]), "r"(a[3]), "r"(b[0]), "r"(b[1]));
}

// register-A 3-term gemm with x4 B loads. B tile [64 rows][BSTR bytes], lo block at +KLO.
template<int NKC, int BSTR, int KLO>
static __device__ __forceinline__ void gemm3r4(float (*acc)[4],
        const uint32_t (*fh)[4], const uint32_t (*fl)[4], uint32_t bBase) {
    const int lane = threadIdx.x & 31;
    uint32_t bAddr = bBase + (lane & 7) * BSTR + (((lane >> 3) & 1) << 4)
                   + ((lane >> 4) & 1) * 8 * BSTR;
    #pragma unroll
    for (int kc = 0; kc < NKC; ++kc) {
        uint32_t bh[4][4];
        #pragma unroll
        for (int jp = 0; jp < 4; ++jp)
            ldmB4(bh[jp], bAddr + jp * 16 * BSTR + kc * 32);
        #pragma unroll
        for (int jp = 0; jp < 4; ++jp) {
            mma16816(acc[2 * jp],     fh[kc], &bh[jp][0]);
            mma16816(acc[2 * jp + 1], fh[kc], &bh[jp][2]);
        }
        #pragma unroll
        for (int jp = 0; jp < 4; ++jp) {
            mma16816(acc[2 * jp],     fl[kc], &bh[jp][0]);
            mma16816(acc[2 * jp + 1], fl[kc], &bh[jp][2]);
        }
        #pragma unroll
        for (int jp = 0; jp < 4; ++jp) {
            uint32_t bl[4];
            ldmB4(bl, bAddr + jp * 16 * BSTR + kc * 32 + KLO);
            mma16816(acc[2 * jp],     fh[kc], &bl[0]);
            mma16816(acc[2 * jp + 1], fh[kc], &bl[2]);
        }
    }
}

// tile-A 3-term gemm with x4 B loads (head only). A tile lo block at +NKC*32 bytes.
template<int NKC, int BSTR, int KLO>
static __device__ void gemm3t(float (*acc)[4], uint32_t aBase, int aStrB, uint32_t bBase) {
    const int lane = threadIdx.x & 31;
    const int KB = NKC * 32;
    uint32_t aAddr = aBase + (lane & 15) * aStrB + ((lane >> 4) << 4);
    uint32_t bAddr = bBase + (lane & 7) * BSTR + (((lane >> 3) & 1) << 4)
                   + ((lane >> 4) & 1) * 8 * BSTR;
    #pragma unroll
    for (int kc = 0; kc < NKC; ++kc) {
        uint32_t ah[4], al[4];
        ldmA(ah, aAddr + kc * 32);
        ldmA(al, aAddr + kc * 32 + KB);
        uint32_t bh[4][4];
        #pragma unroll
        for (int jp = 0; jp < 4; ++jp)
            ldmB4(bh[jp], bAddr + jp * 16 * BSTR + kc * 32);
        #pragma unroll
        for (int jp = 0; jp < 4; ++jp) {
            mma16816(acc[2 * jp],     ah, &bh[jp][0]);
            mma16816(acc[2 * jp + 1], ah, &bh[jp][2]);
        }
        #pragma unroll
        for (int jp = 0; jp < 4; ++jp) {
            mma16816(acc[2 * jp],     al, &bh[jp][0]);
            mma16816(acc[2 * jp + 1], al, &bh[jp][2]);
        }
        #pragma unroll
        for (int jp = 0; jp < 4; ++jp) {
            uint32_t bl[4];
            ldmB4(bl, bAddr + jp * 16 * BSTR + kc * 32 + KLO);
            mma16816(acc[2 * jp],     ah, &bl[0]);
            mma16816(acc[2 * jp + 1], ah, &bl[2]);
        }
    }
}

// convert fp32 pair -> packed bf16 hi + packed bf16 lo
static __device__ __forceinline__ void cvt_pair(float v0, float v1, uint32_t& h, uint32_t& l) {
    __nv_bfloat162 hb = __floats2bfloat162_rn(v0, v1);
    h = *reinterpret_cast<uint32_t*>(&hb);
    float r0 = v0 - __bfloat162float(hb.x);
    float r1 = v1 - __bfloat162float(hb.y);
    __nv_bfloat162 lb = __floats2bfloat162_rn(r0, r1);
    l = *reinterpret_cast<uint32_t*>(&lb);
}

// build m16n8k16 A fragments (hi+lo) from register values v[rowhalf][j][2]
static __device__ __forceinline__ void build_fr(const float v[2][8][2],
                                                uint32_t fh[4][4], uint32_t fl[4][4]) {
    #pragma unroll
    for (int kc = 0; kc < 4; ++kc)
        #pragma unroll
        for (int m = 0; m < 4; ++m) {
            int h = m & 1, j = 2 * kc + (m >> 1);
            cvt_pair(v[h][j][0], v[h][j][1], fh[kc][m], fl[kc][m]);
        }
}

// hi/lo bf16 pair store into padded tile [r][strideElems], hi cols 0:K, lo K:2K
static __device__ __forceinline__ void st_hilo(char* sm, uint32_t off, int strideElems,
                                               int r, int c, int K, float f0, float f1) {
    uint32_t hh, ll;
    cvt_pair(f0, f1, hh, ll);
    __nv_bfloat16* row = (__nv_bfloat16*)(sm + off) + (size_t)r * strideElems;
    *reinterpret_cast<uint32_t*>(row + c)     = hh;
    *reinterpret_cast<uint32_t*>(row + K + c) = ll;
}

// ---------------- cp.async ----------------
#define CP16(dst, src) asm volatile("cp.async.cg.shared.global [%0], [%1], 16;" \
                                    :: "r"(dst), "l"(src) : "memory")
#define CP_COMMIT() asm volatile("cp.async.commit_group;" ::: "memory")
#define CP_WAIT0()  asm volatile("cp.async.wait_group 0;" ::: "memory")
#define CP_WAIT1()  asm volatile("cp.async.wait_group 1;" ::: "memory")

static __device__ __forceinline__ void stage_cp(uint32_t dst, const unsigned char* src,
                                                int bytes, int tid) {
    for (int o = tid * 16; o < bytes; o += 256 * 16)
        CP16(dst + o, src + o);
}

// =====================================================================================
// Kernel 1: convert all weights to hi/lo tile images (27 blocks)
// =====================================================================================
__global__ void conv_w_kernel(const float* __restrict__ in_w, const float* __restrict__ out_w,
                              const float* __restrict__ ff1_w, const float* __restrict__ ff2_w,
                              const float* __restrict__ h1_w, const float* __restrict__ upw,
                              const float* __restrict__ ipw)
{
    int b = blockIdx.x;
    if (b < 24) {
        int l = b / 12, c = b % 12;
        const float* src; int rs;
        if (c < 3)       { src = in_w  + ((size_t)l * 192 + 64 * c) * 64; rs = 64; }
        else if (c == 3) { src = out_w + (size_t)l * 4096;                rs = 64; }
        else {
            int cc = (c - 4) >> 1;
            if (((c - 4) & 1) == 0) { src = ff1_w + ((size_t)l * 256 + 64 * cc) * 64; rs = 64;  }
            else                    { src = ff2_w + (size_t)l * 16384 + 64 * cc;      rs = 256; }
        }
        unsigned char* dst = g_wbuf + (size_t)b * 17408;
        for (int idx = threadIdx.x; idx < 64 * 32; idx += 256) {
            int n = idx >> 5, k2 = (idx & 31) << 1;
            float2 f = *reinterpret_cast<const float2*>(src + (size_t)n * rs + k2);
            uint32_t hh, ll;
            cvt_pair(f.x, f.y, hh, ll);
            *reinterpret_cast<uint32_t*>(dst + n * 272 + k2 * 2)       = hh;
            *reinterpret_cast<uint32_t*>(dst + n * 272 + 128 + k2 * 2) = ll;
        }
    } else {
        const float* src = (b == 24) ? h1_w : (b == 25 ? upw : ipw);
        unsigned char* dst = g_wbuf + WOFF_H1 + (size_t)(b - 24) * 33792;
        for (int idx = threadIdx.x; idx < 64 * 64; idx += 256) {
            int n = idx >> 6, k2 = (idx & 63) << 1;
            float2 f = *reinterpret_cast<const float2*>(src + (size_t)n * 128 + k2);
            uint32_t hh, ll;
            cvt_pair(f.x, f.y, hh, ll);
            *reinterpret_cast<uint32_t*>(dst + n * 528 + k2 * 2)       = hh;
            *reinterpret_cast<uint32_t*>(dst + n * 528 + 256 + k2 * 2) = ll;
        }
    }
}

// =====================================================================================
// Kernel 2: embedding. Features -> register A-fragments; weights cp.async'd preconverted.
// =====================================================================================
#define EB_SMEM 67584u

__global__ void __launch_bounds__(256, 2)
embed_kernel(const int* __restrict__ user_idx, const int* __restrict__ item_idx,
             const float* __restrict__ user_features, const float* __restrict__ item_features,
             const float* __restrict__ user_table, const float* __restrict__ item_table,
             const float* __restrict__ upb, const float* __restrict__ ipb,
             const float* __restrict__ pe)
{
    extern __shared__ char sm[];
    const int tid = threadIdx.x, lane = tid & 31, w = tid >> 5;
    const int qr = lane >> 2, qc = lane & 3;
    const int s0 = blockIdx.x << 6;

    stage_cp(smem_u32(sm), g_wbuf + WOFF_UPW, 67584, tid);
    CP_COMMIT();

    const int side = w >> 2;
    const int r0 = 16 * w + qr;
    const int sA = side ? r0 - 64 : r0;
    const int sB = sA + 8;
    const float* featp = side ? item_features : user_features;
    const float* fpA = featp + (size_t)(s0 + sA) * 128;
    const float* fpB = featp + (size_t)(s0 + sB) * 128;

    uint32_t fh[8][4], fl[8][4];
    #pragma unroll
    for (int kc = 0; kc < 8; ++kc)
        #pragma unroll
        for (int m = 0; m < 4; ++m) {
            const float* p = (m & 1) ? fpB : fpA;
            int col = 16 * kc + 8 * (m >> 1) + 2 * qc;
            float2 f = __ldg(reinterpret_cast<const float2*>(p + col));
            cvt_pair(f.x, f.y, fh[kc][m], fl[kc][m]);
        }

    int myIdxA = side ? __ldg(item_idx + s0 + sA) : __ldg(user_idx + s0 + sA);
    int myIdxB = side ? __ldg(item_idx + s0 + sB) : __ldg(user_idx + s0 + sB);

    CP_WAIT0();
    __syncthreads();

    float acc[8][4];
    #pragma unroll
    for (int j = 0; j < 8; ++j) { acc[j][0] = acc[j][1] = acc[j][2] = acc[j][3] = 0.f; }
    gemm3r4<8, 528, 256>(acc, fh, fl, smem_u32(sm) + (side ? 33792u : 0u));

    const float* bb  = side ? ipb : upb;
    const float* tbl = side ? item_table : user_table;
    const float* pep = pe + side * 64;
    size_t tA = (size_t)myIdxA * 64;
    size_t tB = (size_t)myIdxB * 64;
    float* dA = g_x0 + ((size_t)(s0 + sA) * 2 + side) * 64;
    float* dB = g_x0 + ((size_t)(s0 + sB) * 2 + side) * 64;
    #pragma unroll
    for (int j = 0; j < 8; ++j) {
        int c = 8 * j + 2 * qc;
        dA[c]     = acc[j][0] + __ldg(bb + c)     + __ldg(tbl + tA + c)     + __ldg(pep + c);
        dA[c + 1] = acc[j][1] + __ldg(bb + c + 1) + __ldg(tbl + tA + c + 1) + __ldg(pep + c + 1);
        dB[c]     = acc[j][2] + __ldg(bb + c)     + __ldg(tbl + tB + c)     + __ldg(pep + c);
        dB[c + 1] = acc[j][3] + __ldg(bb + c + 1) + __ldg(tbl + tB + c + 1) + __ldg(pep + c + 1);
    }
}

// =====================================================================================
// Kernel 3: main transformer. 256 threads, 64 samples, register-resident activations.
// smem: XT head tile [64][528B] @0 | WB ring 3x52224 @33792   total 190464
// 3-slot ring, prefetch distance 2; phases: per layer {qkv, out, ff0..ff3}, head (=12).
// =====================================================================================
#define XT_OFF 0u
#define WB_OFF 33792u
#define SLOT_SZ 52224u
#define MAIN_SMEM (33792u + 3u * SLOT_SZ)
#define MT 256

static __device__ __forceinline__ void phase_src(int p, int& off, int& bytes) {
    if (p == 12) { off = WOFF_H1; bytes = 33792; return; }
    int l = p / 6, k = p % 6;
    int ch = l * 12 + (k == 0 ? 0 : (k == 1 ? 3 : 4 + 2 * (k - 2)));
    off = ch * 17408;
    bytes = (k == 0 ? 52224 : (k == 1 ? 17408 : 34816));
}

// register-only LayerNorm over one 64-wide row spread across 4 qc lanes
static __device__ __forceinline__ void ln_reg(float v[8][2], const float* g, const float* b, int qc) {
    float s = 0.f;
    #pragma unroll
    for (int j = 0; j < 8; ++j) s += v[j][0] + v[j][1];
    s += __shfl_xor_sync(0xffffffffu, s, 1);
    s += __shfl_xor_sync(0xffffffffu, s, 2);
    float m = s * (1.f / 64.f);
    float var = 0.f;
    #pragma unroll
    for (int j = 0; j < 8; ++j) {
        float d0 = v[j][0] - m, d1 = v[j][1] - m;
        var += d0 * d0 + d1 * d1;
    }
    var += __shfl_xor_sync(0xffffffffu, var, 1);
    var += __shfl_xor_sync(0xffffffffu, var, 2);
    float inv = rsqrtf(var * (1.f / 64.f) + 1e-5f);
    #pragma unroll
    for (int j = 0; j < 8; ++j) {
        int cc = 8 * j + 2 * qc;
        v[j][0] = (v[j][0] - m) * inv * __ldg(g + cc)     + __ldg(b + cc);
        v[j][1] = (v[j][1] - m) * inv * __ldg(g + cc + 1) + __ldg(b + cc + 1);
    }
}

__global__ void __launch_bounds__(MT, 1)
main_kernel(const float* __restrict__ in_b, const float* __restrict__ out_b,
            const float* __restrict__ ln1_g, const float* __restrict__ ln1_b,
            const float* __restrict__ ff1_b, const float* __restrict__ ff2_b,
            const float* __restrict__ ln2_g, const float* __restrict__ ln2_b,
            const float* __restrict__ h1_b, const float* __restrict__ h2_w,
            const float* __restrict__ h2_b, float* __restrict__ out)
{
    extern __shared__ char sm[];
    const int tid = threadIdx.x, lane = tid & 31, w = tid >> 5;
    const int qr = lane >> 2, qc = lane & 3;
    const int rA = 16 * w + qr;
    const int s0m = blockIdx.x << 6;
    const uint32_t xt_u = smem_u32(sm + XT_OFF);
    const uint32_t wb_u = smem_u32(sm + WB_OFF);
    const uint32_t slot[3] = { wb_u, wb_u + SLOT_SZ, wb_u + 2u * SLOT_SZ };

    // prime the pipeline: fetch phases 0 and 1
    {
        int off, by;
        phase_src(0, off, by);
        stage_cp(slot[0], g_wbuf + off, by, tid);
        CP_COMMIT();
        phase_src(1, off, by);
        stage_cp(slot[1], g_wbuf + off, by, tid);
        CP_COMMIT();
    }

    float x_[2][8][2];
    {
        const float* x0p = g_x0 + (size_t)(blockIdx.x * 128) * 64;
        #pragma unroll
        for (int h = 0; h < 2; ++h) {
            const float* xp = x0p + (size_t)(rA + 8 * h) * 64;
            #pragma unroll
            for (int j = 0; j < 8; ++j) {
                float2 f = __ldg(reinterpret_cast<const float2*>(xp + 8 * j + 2 * qc));
                x_[h][j][0] = f.x; x_[h][j][1] = f.y;
            }
        }
    }

    uint32_t fxh[4][4], fxl[4][4];
    build_fr(x_, fxh, fxl);

    float accF[8][4];
    uint32_t fch[4][4], fcl[4][4];
    int pid = 0;

    for (int l = 0; l < 2; ++l) {
        for (int k = 0; k < 6; ++k) {
            // wait for fetch(pid): at most fetch(pid+1) may stay pending
            CP_WAIT1();
            __syncthreads();
            if (pid + 2 <= 12) {
                int off, by; phase_src(pid + 2, off, by);
                stage_cp(slot[(pid + 2) % 3], g_wbuf + off, by, tid);
                CP_COMMIT();
            }
            const uint32_t bb = slot[pid % 3];

            if (k == 0) {
                // ======== qkv: issue all 144 MMAs back-to-back, then softmax/ctx ========
                float q_[8][4], kacc[8][4], vacc[8][4];
                #pragma unroll
                for (int j = 0; j < 8; ++j) {
                    q_[j][0] = q_[j][1] = q_[j][2] = q_[j][3] = 0.f;
                    kacc[j][0] = kacc[j][1] = kacc[j][2] = kacc[j][3] = 0.f;
                    vacc[j][0] = vacc[j][1] = vacc[j][2] = vacc[j][3] = 0.f;
                }
                gemm3r4<4, 272, 128>(q_,   fxh, fxl, bb);
                gemm3r4<4, 272, 128>(kacc, fxh, fxl, bb + 17408u);
                gemm3r4<4, 272, 128>(vacc, fxh, fxl, bb + 34816u);

                const float* bq = in_b + l * 192;
                const float* bk = bq + 64;
                const float* bv = bq + 128;
                #pragma unroll
                for (int j = 0; j < 8; ++j) {
                    int c = 8 * j + 2 * qc;
                    float q0 = __ldg(bq + c), q1 = __ldg(bq + c + 1);
                    float k0 = __ldg(bk + c), k1 = __ldg(bk + c + 1);
                    q_[j][0] += q0; q_[j][1] += q1; q_[j][2] += q0; q_[j][3] += q1;
                    kacc[j][0] += k0; kacc[j][1] += k1; kacc[j][2] += k0; kacc[j][3] += k1;
                }
                float wS[2][4], wO[2][4];
                {
                    float sS[2][4], sO[2][4];
                    #pragma unroll
                    for (int h = 0; h < 4; ++h) {
                        int j0 = 2 * h, j1 = 2 * h + 1;
                        sS[0][h] = q_[j0][0] * kacc[j0][0] + q_[j0][1] * kacc[j0][1]
                                 + q_[j1][0] * kacc[j1][0] + q_[j1][1] * kacc[j1][1];
                        sS[1][h] = q_[j0][2] * kacc[j0][2] + q_[j0][3] * kacc[j0][3]
                                 + q_[j1][2] * kacc[j1][2] + q_[j1][3] * kacc[j1][3];
                        float k00 = __shfl_xor_sync(0xffffffffu, kacc[j0][0], 4);
                        float k01 = __shfl_xor_sync(0xffffffffu, kacc[j0][1], 4);
                        float k10 = __shfl_xor_sync(0xffffffffu, kacc[j1][0], 4);
                        float k11 = __shfl_xor_sync(0xffffffffu, kacc[j1][1], 4);
                        float k02 = __shfl_xor_sync(0xffffffffu, kacc[j0][2], 4);
                        float k03 = __shfl_xor_sync(0xffffffffu, kacc[j0][3], 4);
                        float k12 = __shfl_xor_sync(0xffffffffu, kacc[j1][2], 4);
                        float k13 = __shfl_xor_sync(0xffffffffu, kacc[j1][3], 4);
                        sO[0][h] = q_[j0][0] * k00 + q_[j0][1] * k01 + q_[j1][0] * k10 + q_[j1][1] * k11;
                        sO[1][h] = q_[j0][2] * k02 + q_[j0][3] * k03 + q_[j1][2] * k12 + q_[j1][3] * k13;
                    }
                    #pragma unroll
                    for (int r = 0; r < 2; ++r)
                        #pragma unroll
                        for (int h = 0; h < 4; ++h) {
                            sS[r][h] += __shfl_xor_sync(0xffffffffu, sS[r][h], 1);
                            sS[r][h] += __shfl_xor_sync(0xffffffffu, sS[r][h], 2);
                            sO[r][h] += __shfl_xor_sync(0xffffffffu, sO[r][h], 1);
                            sO[r][h] += __shfl_xor_sync(0xffffffffu, sO[r][h], 2);
                            float a = sS[r][h] * 0.25f, o = sO[r][h] * 0.25f;
                            float m = fmaxf(a, o);
                            float ea = __expf(a - m), eo = __expf(o - m);
                            float inv = __fdividef(1.f, ea + eo);
                            wS[r][h] = ea * inv; wO[r][h] = eo * inv;
                        }
                }
                const float* bvp = bv;
                #pragma unroll
                for (int j = 0; j < 8; ++j) {
                    int c = 8 * j + 2 * qc;
                    float b0 = __ldg(bvp + c), b1 = __ldg(bvp + c + 1);
                    vacc[j][0] += b0; vacc[j][1] += b1; vacc[j][2] += b0; vacc[j][3] += b1;
                }
                #pragma unroll
                for (int j = 0; j < 8; ++j) {
                    int h = j >> 1;
                    float p0 = __shfl_xor_sync(0xffffffffu, vacc[j][0], 4);
                    float p1 = __shfl_xor_sync(0xffffffffu, vacc[j][1], 4);
                    float p2 = __shfl_xor_sync(0xffffffffu, vacc[j][2], 4);
                    float p3 = __shfl_xor_sync(0xffffffffu, vacc[j][3], 4);
                    float c00 = wS[0][h] * vacc[j][0] + wO[0][h] * p0;
                    float c01 = wS[0][h] * vacc[j][1] + wO[0][h] * p1;
                    float c10 = wS[1][h] * vacc[j][2] + wO[1][h] * p2;
                    float c11 = wS[1][h] * vacc[j][3] + wO[1][h] * p3;
                    int kc = j >> 1, jh = j & 1;
                    cvt_pair(c00, c01, fch[kc][(jh << 1) | 0], fcl[kc][(jh << 1) | 0]);
                    cvt_pair(c10, c11, fch[kc][(jh << 1) | 1], fcl[kc][(jh << 1) | 1]);
                }
            } else if (k == 1) {
                // ======== out-proj + residual + LN1 ========
                float acc[8][4];
                #pragma unroll
                for (int j = 0; j < 8; ++j) { acc[j][0] = acc[j][1] = acc[j][2] = acc[j][3] = 0.f; }
                gemm3r4<4, 272, 128>(acc, fch, fcl, bb);
                const float* bo = out_b + l * 64;
                #pragma unroll
                for (int j = 0; j < 8; ++j) {
                    int c = 8 * j + 2 * qc;
                    float b0 = __ldg(bo + c), b1 = __ldg(bo + c + 1);
                    x_[0][j][0] += acc[j][0] + b0; x_[0][j][1] += acc[j][1] + b1;
                    x_[1][j][0] += acc[j][2] + b0; x_[1][j][1] += acc[j][3] + b1;
                }
                ln_reg(x_[0], ln1_g + l * 64, ln1_b + l * 64, qc);
                ln_reg(x_[1], ln1_g + l * 64, ln1_b + l * 64, qc);
                build_fr(x_, fxh, fxl);
            } else {
                // ======== ff pair ========
                int c4 = k - 2;
                float acc[8][4];
                #pragma unroll
                for (int j = 0; j < 8; ++j) { acc[j][0] = acc[j][1] = acc[j][2] = acc[j][3] = 0.f; }
                gemm3r4<4, 272, 128>(acc, fxh, fxl, bb);
                const float* b1p = ff1_b + l * 256 + 64 * c4;
                #pragma unroll
                for (int j = 0; j < 8; ++j) {
                    int c = 8 * j + 2 * qc;
                    float b0 = __ldg(b1p + c), b1 = __ldg(b1p + c + 1);
                    float h00 = fmaxf(acc[j][0] + b0, 0.f), h01 = fmaxf(acc[j][1] + b1, 0.f);
                    float h10 = fmaxf(acc[j][2] + b0, 0.f), h11 = fmaxf(acc[j][3] + b1, 0.f);
                    int kc = j >> 1, jh = j & 1;
                    cvt_pair(h00, h01, fch[kc][(jh << 1) | 0], fcl[kc][(jh << 1) | 0]);
                    cvt_pair(h10, h11, fch[kc][(jh << 1) | 1], fcl[kc][(jh << 1) | 1]);
                }
                if (c4 == 0) {
                    #pragma unroll
                    for (int j = 0; j < 8; ++j) { accF[j][0] = accF[j][1] = accF[j][2] = accF[j][3] = 0.f; }
                }
                gemm3r4<4, 272, 128>(accF, fch, fcl, bb + 17408u);
                if (c4 == 3) {
                    const float* b2 = ff2_b + l * 64;
                    #pragma unroll
                    for (int j = 0; j < 8; ++j) {
                        int c = 8 * j + 2 * qc;
                        float b0 = __ldg(b2 + c), b1 = __ldg(b2 + c + 1);
                        x_[0][j][0] += accF[j][0] + b0; x_[0][j][1] += accF[j][1] + b1;
                        x_[1][j][0] += accF[j][2] + b0; x_[1][j][1] += accF[j][3] + b1;
                    }
                    ln_reg(x_[0], ln2_g + l * 64, ln2_b + l * 64, qc);
                    ln_reg(x_[1], ln2_g + l * 64, ln2_b + l * 64, qc);
                    if (l == 0) {
                        build_fr(x_, fxh, fxl);
                    } else {
                        #pragma unroll
                        for (int h = 0; h < 2; ++h) {
                            int row = (rA + 8 * h) >> 1;
                            int cb  = 64 * ((rA + 8 * h) & 1);
                            #pragma unroll
                            for (int j = 0; j < 8; ++j) {
                                int c = 8 * j + 2 * qc;
                                st_hilo(sm, XT_OFF, 264, row, cb + c, 128,
                                        x_[h][j][0], x_[h][j][1]);
                            }
                        }
                    }
                }
            }
            ++pid;
        }
    }

    // ================= head (phase 12, slot[0]) =================
    CP_WAIT0();
    __syncthreads();

    if (w < 4) {
        float acc[8][4];
        #pragma unroll
        for (int j = 0; j < 8; ++j) { acc[j][0] = acc[j][1] = acc[j][2] = acc[j][3] = 0.f; }
        gemm3t<8, 528, 256>(acc, xt_u + (uint32_t)(16 * w) * 528u, 528, slot[0]);
        float pA = 0.f, pB = 0.f;
        #pragma unroll
        for (int j = 0; j < 8; ++j) {
            int c = 8 * j + 2 * qc;
            float b0 = __ldg(h1_b + c), b1 = __ldg(h1_b + c + 1);
            float w0 = __ldg(h2_w + c), w1 = __ldg(h2_w + c + 1);
            pA += fmaxf(acc[j][0] + b0, 0.f) * w0 + fmaxf(acc[j][1] + b1, 0.f) * w1;
            pB += fmaxf(acc[j][2] + b0, 0.f) * w0 + fmaxf(acc[j][3] + b1, 0.f) * w1;
        }
        pA += __shfl_xor_sync(0xffffffffu, pA, 1);
        pA += __shfl_xor_sync(0xffffffffu, pA, 2);
        pB += __shfl_xor_sync(0xffffffffu, pB, 1);
        pB += __shfl_xor_sync(0xffffffffu, pB, 2);
        if (qc == 0) {
            float hb = __ldg(h2_b);
            out[s0m + 16 * w + qr]     = pA + hb;
            out[s0m + 16 * w + qr + 8] = pB + hb;
        }
    }
}

// =====================================================================================
extern "C" void kernel_launch(void* const* d_in, const int* in_sizes, int n_in,
                              void* d_out, int out_size)
{
    const int*   user_idx      = (const int*)  d_in[0];
    const int*   item_idx      = (const int*)  d_in[1];
    const float* user_features = (const float*)d_in[2];
    const float* item_features = (const float*)d_in[3];
    const float* user_table    = (const float*)d_in[4];
    const float* item_table    = (const float*)d_in[5];
    const float* upw           = (const float*)d_in[6];
    const float* upb           = (const float*)d_in[7];
    const float* ipw           = (const float*)d_in[8];
    const float* ipb           = (const float*)d_in[9];
    const float* pe            = (const float*)d_in[10];
    const float* in_w          = (const float*)d_in[11];
    const float* in_b          = (const float*)d_in[12];
    const float* out_w         = (const float*)d_in[13];
    const float* out_b         = (const float*)d_in[14];
    const float* ln1_g         = (const float*)d_in[15];
    const float* ln1_b         = (const float*)d_in[16];
    const float* ff1_w         = (const float*)d_in[17];
    const float* ff1_b         = (const float*)d_in[18];
    const float* ff2_w         = (const float*)d_in[19];
    const float* ff2_b         = (const float*)d_in[20];
    const float* ln2_g         = (const float*)d_in[21];
    const float* ln2_b         = (const float*)d_in[22];
    const float* h1_w          = (const float*)d_in[23];
    const float* h1_b          = (const float*)d_in[24];
    const float* h2_w          = (const float*)d_in[25];
    const float* h2_b          = (const float*)d_in[26];
    float* out = (float*)d_out;

    const int B = in_sizes[0];

    static bool attr_set = false;
    if (!attr_set) {
        cudaFuncSetAttribute(embed_kernel, cudaFuncAttributeMaxDynamicSharedMemorySize, EB_SMEM);
        cudaFuncSetAttribute(main_kernel,  cudaFuncAttributeMaxDynamicSharedMemorySize, MAIN_SMEM);
        attr_set = true;
    }

    conv_w_kernel<<<27, 256>>>(in_w, out_w, ff1_w, ff2_w, h1_w, upw, ipw);
    embed_kernel<<<B / 64, 256, EB_SMEM>>>(user_idx, item_idx, user_features, item_features,
                                           user_table, item_table, upb, ipb, pe);
    main_kernel<<<B / 64, MT, MAIN_SMEM>>>(in_b, out_b, ln1_g, ln1_b, ff1_b, ff2_b,
                                           ln2_g, ln2_b, h1_b, h2_w, h2_b, out);
}